// round 9
// baseline (speedup 1.0000x reference)
#include <cuda_runtime.h>
#include <cstdint>

#define T_    512
#define F_    32
#define E_    16
#define H_    128
#define KX_   48
#define CL_   4
#define UN_   32
#define RWS_  32
#define NCTA  128
#define NTHR  512   // tid = rq*128 + u*4 + kq

typedef unsigned long long u64;

// SMEM (floats). Weights: [kk][gate_type][u][kq][4] -> kk*1536 + gt*512 + u*16 + kq*4
#define OFF_WIH0 0
#define OFF_WHH0 (OFF_WIH0 + 3*1536)
#define OFF_WIH1 (OFF_WHH0 + 8*1536)
#define OFF_WHH1 (OFF_WIH1 + 8*1536)
#define OFF_H0   (OFF_WHH1 + 8*1536)          // 2 buffers
#define OFF_H1   (OFF_H0 + 2*RWS_*H_)         // single buffer
#define OFF_X    (OFF_H1 + RWS_*H_)           // single buffer
#define SMEM_FLOATS (OFF_X + RWS_*KX_)
#define SMEM_BYTES  (SMEM_FLOATS * 4)         // 221184

__device__ __forceinline__ u64 fma2(u64 a, u64 b, u64 c) {
    u64 d;
    asm("fma.rn.f32x2 %0, %1, %2, %3;" : "=l"(d) : "l"(a), "l"(b), "l"(c));
    return d;
}
__device__ __forceinline__ float hsum2(u64 a) {
    float l, h;
    asm("mov.b64 {%0, %1}, %2;" : "=f"(l), "=f"(h) : "l"(a));
    return l + h;
}
__device__ __forceinline__ float sigmoidf_(float v) {
    return 1.f / (1.f + __expf(-v));
}
__device__ __forceinline__ float tanhf_(float v) {
    v = fminf(fmaxf(v, -15.f), 15.f);
    float e = __expf(2.f * v);
    return (e - 1.f) / (e + 1.f);
}
__device__ __forceinline__ uint32_t smem_u32(const void* p) {
    uint32_t a;
    asm("{ .reg .u64 t; cvta.to.shared.u64 t, %1; cvt.u32.u64 %0, t; }"
        : "=r"(a) : "l"(p));
    return a;
}
__device__ __forceinline__ void st_cluster_f32(uint32_t laddr, int rank, float v) {
    asm volatile(
        "{ .reg .b32 ra;\n\t"
        "mapa.shared::cluster.u32 ra, %0, %1;\n\t"
        "st.shared::cluster.f32 [ra], %2; }"
        :: "r"(laddr), "r"(rank), "f"(v) : "memory");
}
#define CLUSTER_SYNC() do { \
    asm volatile("barrier.cluster.arrive.aligned;" ::: "memory"); \
    asm volatile("barrier.cluster.wait.aligned;"   ::: "memory"); \
} while (0)

// ---- pass 1: r,z accumulation over one 8-row block ----
template<int NIH, int SIH>
__device__ __forceinline__ void accum_rz(
    const float* __restrict__ Wih, const float* __restrict__ Whh,
    const float* __restrict__ vih, const float* __restrict__ vhh,
    int tb, int kqo, u64* __restrict__ Ar, u64* __restrict__ Az)
{
#pragma unroll
    for (int r = 0; r < 8; ++r) { Ar[r] = 0; Az[r] = 0; }
#pragma unroll
    for (int kk = 0; kk < NIH; ++kk) {
        const float* wp = Wih + kk * 1536 + tb;
        ulonglong2 wr = *(const ulonglong2*)wp;
        ulonglong2 wz = *(const ulonglong2*)(wp + 512);
#pragma unroll
        for (int r = 0; r < 8; ++r) {
            ulonglong2 v = *(const ulonglong2*)(vih + r * SIH + kk * 16 + kqo);
            Ar[r] = fma2(wr.x, v.x, Ar[r]); Ar[r] = fma2(wr.y, v.y, Ar[r]);
            Az[r] = fma2(wz.x, v.x, Az[r]); Az[r] = fma2(wz.y, v.y, Az[r]);
        }
    }
#pragma unroll
    for (int kk = 0; kk < 8; ++kk) {
        const float* wp = Whh + kk * 1536 + tb;
        ulonglong2 wr = *(const ulonglong2*)wp;
        ulonglong2 wz = *(const ulonglong2*)(wp + 512);
#pragma unroll
        for (int r = 0; r < 8; ++r) {
            ulonglong2 v = *(const ulonglong2*)(vhh + r * H_ + kk * 16 + kqo);
            Ar[r] = fma2(wr.x, v.x, Ar[r]); Ar[r] = fma2(wr.y, v.y, Ar[r]);
            Az[r] = fma2(wz.x, v.x, Az[r]); Az[r] = fma2(wz.y, v.y, Az[r]);
        }
    }
}
// ---- pass 2: n-gate accumulation (ih and hh parts kept separate) ----
template<int NIH, int SIH>
__device__ __forceinline__ void accum_n(
    const float* __restrict__ Wih, const float* __restrict__ Whh,
    const float* __restrict__ vih, const float* __restrict__ vhh,
    int tb, int kqo, u64* __restrict__ Ax, u64* __restrict__ Ah)
{
#pragma unroll
    for (int r = 0; r < 8; ++r) { Ax[r] = 0; Ah[r] = 0; }
#pragma unroll
    for (int kk = 0; kk < NIH; ++kk) {
        ulonglong2 wn = *(const ulonglong2*)(Wih + kk * 1536 + 1024 + tb);
#pragma unroll
        for (int r = 0; r < 8; ++r) {
            ulonglong2 v = *(const ulonglong2*)(vih + r * SIH + kk * 16 + kqo);
            Ax[r] = fma2(wn.x, v.x, Ax[r]); Ax[r] = fma2(wn.y, v.y, Ax[r]);
        }
    }
#pragma unroll
    for (int kk = 0; kk < 8; ++kk) {
        ulonglong2 wn = *(const ulonglong2*)(Whh + kk * 1536 + 1024 + tb);
#pragma unroll
        for (int r = 0; r < 8; ++r) {
            ulonglong2 v = *(const ulonglong2*)(vhh + r * H_ + kk * 16 + kqo);
            Ah[r] = fma2(wn.x, v.x, Ah[r]); Ah[r] = fma2(wn.y, v.y, Ah[r]);
        }
    }
}

#define RED4(kout, s) \
    _Pragma("unroll") \
    for (int rr = 0; rr < 4; ++rr) { \
        float snd = hiK ? (s)[rr] : (s)[4 + rr]; \
        float kp  = hiK ? (s)[4 + rr] : (s)[rr]; \
        (kout)[rr] = kp + __shfl_xor_sync(0xffffffffu, snd, 2, 4); }
#define RED2(f, kin, rr) { \
        float snd = hiP ? (kin)[rr] : (kin)[2 + rr]; \
        float kp  = hiP ? (kin)[2 + rr] : (kin)[rr]; \
        f = kp + __shfl_xor_sync(0xffffffffu, snd, 1, 4); }

// reduce r,z across kq; lane kq keeps R,Z for its rows 2kq, 2kq+1
__device__ __forceinline__ void finalize_rz(
    const u64* Ar, const u64* Az, float br, float bz,
    bool hiK, bool hiP, float* R, float* Z)
{
    float sr[8], sz[8];
#pragma unroll
    for (int r = 0; r < 8; ++r) { sr[r] = hsum2(Ar[r]); sz[r] = hsum2(Az[r]); }
    float kr[4], kz[4];
    RED4(kr, sr); RED4(kz, sz);
#pragma unroll
    for (int rr = 0; rr < 2; ++rr) {
        float fr, fz;
        RED2(fr, kr, rr); RED2(fz, kz, rr);
        R[rr] = sigmoidf_(fr + br);
        Z[rr] = sigmoidf_(fz + bz);
    }
}
// reduce n across kq; combine with R,Z; update h
__device__ __forceinline__ void finalize_n(
    const u64* Ax, const u64* Ah, float bxn, float bhn,
    bool hiK, bool hiP, const float* R, const float* Z,
    float* hown, float* hout)
{
    float sx[8], sh[8];
#pragma unroll
    for (int r = 0; r < 8; ++r) { sx[r] = hsum2(Ax[r]); sh[r] = hsum2(Ah[r]); }
    float kx[4], kh[4];
    RED4(kx, sx); RED4(kh, sh);
#pragma unroll
    for (int rr = 0; rr < 2; ++rr) {
        float fx, fh;
        RED2(fx, kx, rr); RED2(fh, kh, rr);
        float N = tanhf_(fx + bxn + R[rr] * (fh + bhn));
        float h = N + Z[rr] * (hown[rr] - N);
        hown[rr] = h;
        hout[rr] = h;
    }
}

__global__ void __launch_bounds__(NTHR, 1) gru_kernel(
    const float* __restrict__ x,
    const int*   __restrict__ ticker,
    const float* __restrict__ embed,
    const float* __restrict__ b_ih0, const float* __restrict__ b_hh0,
    const float* __restrict__ b_ih1, const float* __restrict__ b_hh1,
    const float* __restrict__ head_w1, const float* __restrict__ head_b1,
    const float* __restrict__ head_w2, const float* __restrict__ head_b2,
    const float* __restrict__ W_ih0, const float* __restrict__ W_hh0,
    const float* __restrict__ W_ih1, const float* __restrict__ W_hh1,
    float* __restrict__ y)
{
    extern __shared__ __align__(16) float sm[];
    const int tid   = threadIdx.x;
    const int kq    = tid & 3;
    const int u     = (tid >> 2) & 31;
    const int rq    = tid >> 7;
    const int crank = blockIdx.x & 3;
    const int b0    = (blockIdx.x >> 2) * RWS_;

    const int  tb   = u * 16 + kq * 4;
    const int  kqo  = kq * 4;
    const bool hiK  = kq & 2, hiP = kq & 1;
    const int  posu = (u >> 2) * 16 + crank * 4 + (u & 3);
    const int  rowb = rq * 8;

    // ---- one-time weight remap into SMEM ----
    for (int idx = tid; idx < 96 * KX_; idx += NTHR) {
        int g = idx / KX_, k = idx % KX_;
        int gt = g / 32, uu = g & 31;
        int kqq = k / 12, kk = (k % 12) >> 2, i = k & 3;
        sm[OFF_WIH0 + kk * 1536 + gt * 512 + uu * 16 + kqq * 4 + i] =
            W_ih0[(size_t)(gt * H_ + crank * UN_ + uu) * KX_ + k];
    }
    for (int idx = tid; idx < 96 * H_; idx += NTHR) {
        int g = idx / H_, k = idx % H_;
        int gt = g / 32, uu = g & 31;
        int kqq = k >> 5, kk = (k & 31) >> 2, i = k & 3;
        int dst = kk * 1536 + gt * 512 + uu * 16 + kqq * 4 + i;
        size_t grow = (size_t)(gt * H_ + crank * UN_ + uu);
        sm[OFF_WHH0 + dst] = W_hh0[grow * H_ + k];
        sm[OFF_WIH1 + dst] = W_ih1[grow * H_ + k];
        sm[OFF_WHH1 + dst] = W_hh1[grow * H_ + k];
    }
    for (int i = tid; i < 2 * RWS_ * H_; i += NTHR) sm[OFF_H0 + i] = 0.f;
    for (int i = tid; i < RWS_ * H_; i += NTHR)     sm[OFF_H1 + i] = 0.f;
    for (int idx = tid; idx < RWS_ * E_; idx += NTHR) {
        int r = idx >> 4, e = idx & 15, k = F_ + e;
        int kqq = k / 12, kk = (k % 12) >> 2, i = k & 3;
        sm[OFF_X + r * KX_ + kk * 16 + kqq * 4 + i] =
            embed[(size_t)ticker[b0 + r] * E_ + e];
    }
    if (tid < 256) {
        int r = tid >> 3, q = tid & 7;
        int kqq = q / 3, kk = q - 3 * kqq;
        *(float4*)&sm[OFF_X + r * KX_ + kk * 16 + kqq * 4] =
            *(const float4*)(x + ((size_t)(b0 + r) * T_) * F_ + q * 4);
    }
    const int jr = crank * UN_ + u;
    const float br0  = b_ih0[jr] + b_hh0[jr];
    const float bz0  = b_ih0[H_ + jr] + b_hh0[H_ + jr];
    const float bxn0 = b_ih0[2 * H_ + jr], bhn0 = b_hh0[2 * H_ + jr];
    const float br1  = b_ih1[jr] + b_hh1[jr];
    const float bz1  = b_ih1[H_ + jr] + b_hh1[H_ + jr];
    const float bxn1 = b_ih1[2 * H_ + jr], bhn1 = b_hh1[2 * H_ + jr];

    float h0own[2] = {0.f, 0.f};
    float h1own[2] = {0.f, 0.f};

    __syncthreads();
    CLUSTER_SYNC();

    float* xs  = sm + OFF_X;
    float* h1s = sm + OFF_H1;

    for (int t = 0; t < T_; ++t) {
        const float* h0cur = sm + OFF_H0 + (t & 1) * RWS_ * H_;
        float*       h0nxt = sm + OFF_H0 + ((t + 1) & 1) * RWS_ * H_;
        u64 A0[8], A1[8];
        float Rg[2], Zg[2], hA[2];

        // ---------- layer 0 (two passes) ----------
        accum_rz<3, KX_>(sm + OFF_WIH0, sm + OFF_WHH0,
                         xs + rowb * KX_, h0cur + rowb * H_, tb, kqo, A0, A1);
        finalize_rz(A0, A1, br0, bz0, hiK, hiP, Rg, Zg);
        accum_n<3, KX_>(sm + OFF_WIH0, sm + OFF_WHH0,
                        xs + rowb * KX_, h0cur + rowb * H_, tb, kqo, A0, A1);
        finalize_n(A0, A1, bxn0, bhn0, hiK, hiP, Rg, Zg, h0own, hA);
        {
            uint32_t base = smem_u32(h0nxt);
#pragma unroll
            for (int v2 = 0; v2 < 2; ++v2) {
                int row = rowb + 2 * kq + v2;
                uint32_t la = base + (uint32_t)(row * H_ + posu) * 4u;
#pragma unroll
                for (int rk = 0; rk < CL_; ++rk) st_cluster_f32(la, rk, hA[v2]);
            }
        }
        CLUSTER_SYNC();        // S1: h0(t) visible; x(t)/h0cur readers done

        if (t + 1 < T_ && tid < 256) {
            int r = tid >> 3, q = tid & 7;
            int kqq = q / 3, kk = q - 3 * kqq;
            *(float4*)&xs[r * KX_ + kk * 16 + kqq * 4] =
                *(const float4*)(x + ((size_t)(b0 + r) * T_ + t + 1) * F_ + q * 4);
        }

        // ---------- layer 1 (two passes) ----------
        accum_rz<8, H_>(sm + OFF_WIH1, sm + OFF_WHH1,
                        h0nxt + rowb * H_, h1s + rowb * H_, tb, kqo, A0, A1);
        finalize_rz(A0, A1, br1, bz1, hiK, hiP, Rg, Zg);
        accum_n<8, H_>(sm + OFF_WIH1, sm + OFF_WHH1,
                       h0nxt + rowb * H_, h1s + rowb * H_, tb, kqo, A0, A1);
        finalize_n(A0, A1, bxn1, bhn1, hiK, hiP, Rg, Zg, h1own, hA);
        CLUSTER_SYNC();        // S2: everyone finished READING h1(t-1)
        {
            uint32_t base = smem_u32(h1s);
#pragma unroll
            for (int v2 = 0; v2 < 2; ++v2) {
                int row = rowb + 2 * kq + v2;
                uint32_t la = base + (uint32_t)(row * H_ + posu) * 4u;
#pragma unroll
                for (int rk = 0; rk < CL_; ++rk) st_cluster_f32(la, rk, hA[v2]);
            }
        }
        CLUSTER_SYNC();        // S3: h1(t) visible
    }

    // ---------- head: rows [crank*8, crank*8+8) ----------
    float* scratch = xs;
    if (tid < H_) {
        const int uu = tid;
        const float w2  = head_w2[uu];
        const float b1v = head_b1[uu];
        float acc[8];
#pragma unroll
        for (int r = 0; r < 8; ++r) acc[r] = b1v;
#pragma unroll
        for (int kq4 = 0; kq4 < 4; ++kq4)
#pragma unroll
            for (int kk = 0; kk < 8; ++kk) {
                float4 w = *(const float4*)
                    (head_w1 + (size_t)uu * H_ + kq4 * 32 + kk * 4);
#pragma unroll
                for (int r = 0; r < 8; ++r) {
                    float4 v = *(const float4*)
                        &h1s[(crank * 8 + r) * H_ + kk * 16 + kq4 * 4];
                    acc[r] += w.x * v.x + w.y * v.y + w.z * v.z + w.w * v.w;
                }
            }
#pragma unroll
        for (int r = 0; r < 8; ++r)
            scratch[r * H_ + uu] = fmaxf(acc[r], 0.f) * w2;
    }
    __syncthreads();
    if (tid < 8) {
        float acc = head_b2[0];
        for (int k = 0; k < H_; ++k) acc += scratch[tid * H_ + k];
        y[b0 + crank * 8 + tid] = acc;
    }
}

extern "C" void kernel_launch(void* const* d_in, const int* in_sizes, int n_in,
                              void* d_out, int out_size) {
    const float* x       = (const float*)d_in[0];
    const int*   ticker  = (const int*)  d_in[1];
    const float* embed   = (const float*)d_in[2];
    const float* W_ih0   = (const float*)d_in[3];
    const float* W_hh0   = (const float*)d_in[4];
    const float* b_ih0   = (const float*)d_in[5];
    const float* b_hh0   = (const float*)d_in[6];
    const float* W_ih1   = (const float*)d_in[7];
    const float* W_hh1   = (const float*)d_in[8];
    const float* b_ih1   = (const float*)d_in[9];
    const float* b_hh1   = (const float*)d_in[10];
    const float* head_w1 = (const float*)d_in[11];
    const float* head_b1 = (const float*)d_in[12];
    const float* head_w2 = (const float*)d_in[13];
    const float* head_b2 = (const float*)d_in[14];

    cudaFuncSetAttribute(gru_kernel,
                         cudaFuncAttributeMaxDynamicSharedMemorySize, SMEM_BYTES);

    cudaLaunchConfig_t cfg = {};
    cfg.gridDim  = dim3(NCTA, 1, 1);
    cfg.blockDim = dim3(NTHR, 1, 1);
    cfg.dynamicSmemBytes = SMEM_BYTES;
    cfg.stream = 0;
    cudaLaunchAttribute attr[1];
    attr[0].id = cudaLaunchAttributeClusterDimension;
    attr[0].val.clusterDim.x = CL_;
    attr[0].val.clusterDim.y = 1;
    attr[0].val.clusterDim.z = 1;
    cfg.attrs = attr;
    cfg.numAttrs = 1;

    cudaLaunchKernelEx(&cfg, gru_kernel,
                       x, ticker, embed,
                       b_ih0, b_hh0, b_ih1, b_hh1,
                       head_w1, head_b1, head_w2, head_b2,
                       W_ih0, W_hh0, W_ih1, W_hh1,
                       (float*)d_out);
}

// round 10
// speedup vs baseline: 1.0002x; 1.0002x over previous
#include <cuda_runtime.h>
#include <cstdint>

#define T_    512
#define F_    32
#define E_    16
#define H_    128
#define KX_   48
#define CL_   4
#define UN_   32
#define RWS_  32
#define NCTA  128
#define NTHR  512   // tid = rq*128 + u*4 + kq

typedef unsigned long long u64;

// SMEM (floats). Weights: [kk][gate_type][u][kq][4] -> kk*1536 + gt*512 + u*16 + kq*4
#define OFF_WIH0 0
#define OFF_WHH0 (OFF_WIH0 + 3*1536)
#define OFF_WIH1 (OFF_WHH0 + 8*1536)
#define OFF_WHH1 (OFF_WIH1 + 8*1536)
#define OFF_H0   (OFF_WHH1 + 8*1536)          // 2 buffers
#define OFF_H1   (OFF_H0 + 2*RWS_*H_)         // single buffer
#define OFF_X    (OFF_H1 + RWS_*H_)           // single buffer
#define SMEM_FLOATS (OFF_X + RWS_*KX_)
#define SMEM_BYTES  (SMEM_FLOATS * 4)         // 221184

__device__ __forceinline__ u64 fma2(u64 a, u64 b, u64 c) {
    u64 d;
    asm("fma.rn.f32x2 %0, %1, %2, %3;" : "=l"(d) : "l"(a), "l"(b), "l"(c));
    return d;
}
__device__ __forceinline__ float hsum2(u64 a) {
    float l, h;
    asm("mov.b64 {%0, %1}, %2;" : "=f"(l), "=f"(h) : "l"(a));
    return l + h;
}
__device__ __forceinline__ float sigmoidf_(float v) {
    return 1.f / (1.f + __expf(-v));
}
__device__ __forceinline__ float tanhf_(float v) {
    v = fminf(fmaxf(v, -15.f), 15.f);
    float e = __expf(2.f * v);
    return (e - 1.f) / (e + 1.f);
}
__device__ __forceinline__ uint32_t smem_u32(const void* p) {
    uint32_t a;
    asm("{ .reg .u64 t; cvta.to.shared.u64 t, %1; cvt.u32.u64 %0, t; }"
        : "=r"(a) : "l"(p));
    return a;
}
__device__ __forceinline__ void st_cluster_f32(uint32_t laddr, int rank, float v) {
    asm volatile(
        "{ .reg .b32 ra;\n\t"
        "mapa.shared::cluster.u32 ra, %0, %1;\n\t"
        "st.shared::cluster.f32 [ra], %2; }"
        :: "r"(laddr), "r"(rank), "f"(v) : "memory");
}
#define CLUSTER_SYNC() do { \
    asm volatile("barrier.cluster.arrive.aligned;" ::: "memory"); \
    asm volatile("barrier.cluster.wait.aligned;"   ::: "memory"); \
} while (0)

// ---- pass 1: r,z accumulation over one 8-row block ----
template<int NIH, int SIH>
__device__ __forceinline__ void accum_rz(
    const float* __restrict__ Wih, const float* __restrict__ Whh,
    const float* __restrict__ vih, const float* __restrict__ vhh,
    int tb, int kqo, u64* __restrict__ Ar, u64* __restrict__ Az)
{
#pragma unroll
    for (int r = 0; r < 8; ++r) { Ar[r] = 0; Az[r] = 0; }
#pragma unroll
    for (int kk = 0; kk < NIH; ++kk) {
        const float* wp = Wih + kk * 1536 + tb;
        ulonglong2 wr = *(const ulonglong2*)wp;
        ulonglong2 wz = *(const ulonglong2*)(wp + 512);
#pragma unroll
        for (int r = 0; r < 8; ++r) {
            ulonglong2 v = *(const ulonglong2*)(vih + r * SIH + kk * 16 + kqo);
            Ar[r] = fma2(wr.x, v.x, Ar[r]); Ar[r] = fma2(wr.y, v.y, Ar[r]);
            Az[r] = fma2(wz.x, v.x, Az[r]); Az[r] = fma2(wz.y, v.y, Az[r]);
        }
    }
#pragma unroll
    for (int kk = 0; kk < 8; ++kk) {
        const float* wp = Whh + kk * 1536 + tb;
        ulonglong2 wr = *(const ulonglong2*)wp;
        ulonglong2 wz = *(const ulonglong2*)(wp + 512);
#pragma unroll
        for (int r = 0; r < 8; ++r) {
            ulonglong2 v = *(const ulonglong2*)(vhh + r * H_ + kk * 16 + kqo);
            Ar[r] = fma2(wr.x, v.x, Ar[r]); Ar[r] = fma2(wr.y, v.y, Ar[r]);
            Az[r] = fma2(wz.x, v.x, Az[r]); Az[r] = fma2(wz.y, v.y, Az[r]);
        }
    }
}
// ---- pass 2: n-gate accumulation (ih and hh parts kept separate) ----
template<int NIH, int SIH>
__device__ __forceinline__ void accum_n(
    const float* __restrict__ Wih, const float* __restrict__ Whh,
    const float* __restrict__ vih, const float* __restrict__ vhh,
    int tb, int kqo, u64* __restrict__ Ax, u64* __restrict__ Ah)
{
#pragma unroll
    for (int r = 0; r < 8; ++r) { Ax[r] = 0; Ah[r] = 0; }
#pragma unroll
    for (int kk = 0; kk < NIH; ++kk) {
        ulonglong2 wn = *(const ulonglong2*)(Wih + kk * 1536 + 1024 + tb);
#pragma unroll
        for (int r = 0; r < 8; ++r) {
            ulonglong2 v = *(const ulonglong2*)(vih + r * SIH + kk * 16 + kqo);
            Ax[r] = fma2(wn.x, v.x, Ax[r]); Ax[r] = fma2(wn.y, v.y, Ax[r]);
        }
    }
#pragma unroll
    for (int kk = 0; kk < 8; ++kk) {
        ulonglong2 wn = *(const ulonglong2*)(Whh + kk * 1536 + 1024 + tb);
#pragma unroll
        for (int r = 0; r < 8; ++r) {
            ulonglong2 v = *(const ulonglong2*)(vhh + r * H_ + kk * 16 + kqo);
            Ah[r] = fma2(wn.x, v.x, Ah[r]); Ah[r] = fma2(wn.y, v.y, Ah[r]);
        }
    }
}

#define RED4(kout, s) \
    _Pragma("unroll") \
    for (int rr = 0; rr < 4; ++rr) { \
        float snd = hiK ? (s)[rr] : (s)[4 + rr]; \
        float kp  = hiK ? (s)[4 + rr] : (s)[rr]; \
        (kout)[rr] = kp + __shfl_xor_sync(0xffffffffu, snd, 2, 4); }
#define RED2(f, kin, rr) { \
        float snd = hiP ? (kin)[rr] : (kin)[2 + rr]; \
        float kp  = hiP ? (kin)[2 + rr] : (kin)[rr]; \
        f = kp + __shfl_xor_sync(0xffffffffu, snd, 1, 4); }

// reduce r,z across kq; lane kq keeps R,Z for its rows 2kq, 2kq+1
__device__ __forceinline__ void finalize_rz(
    const u64* Ar, const u64* Az, float br, float bz,
    bool hiK, bool hiP, float* R, float* Z)
{
    float sr[8], sz[8];
#pragma unroll
    for (int r = 0; r < 8; ++r) { sr[r] = hsum2(Ar[r]); sz[r] = hsum2(Az[r]); }
    float kr[4], kz[4];
    RED4(kr, sr); RED4(kz, sz);
#pragma unroll
    for (int rr = 0; rr < 2; ++rr) {
        float fr, fz;
        RED2(fr, kr, rr); RED2(fz, kz, rr);
        R[rr] = sigmoidf_(fr + br);
        Z[rr] = sigmoidf_(fz + bz);
    }
}
// reduce n across kq; combine with R,Z; update h
__device__ __forceinline__ void finalize_n(
    const u64* Ax, const u64* Ah, float bxn, float bhn,
    bool hiK, bool hiP, const float* R, const float* Z,
    float* hown, float* hout)
{
    float sx[8], sh[8];
#pragma unroll
    for (int r = 0; r < 8; ++r) { sx[r] = hsum2(Ax[r]); sh[r] = hsum2(Ah[r]); }
    float kx[4], kh[4];
    RED4(kx, sx); RED4(kh, sh);
#pragma unroll
    for (int rr = 0; rr < 2; ++rr) {
        float fx, fh;
        RED2(fx, kx, rr); RED2(fh, kh, rr);
        float N = tanhf_(fx + bxn + R[rr] * (fh + bhn));
        float h = N + Z[rr] * (hown[rr] - N);
        hown[rr] = h;
        hout[rr] = h;
    }
}

__global__ void __launch_bounds__(NTHR, 1) gru_kernel(
    const float* __restrict__ x,
    const int*   __restrict__ ticker,
    const float* __restrict__ embed,
    const float* __restrict__ b_ih0, const float* __restrict__ b_hh0,
    const float* __restrict__ b_ih1, const float* __restrict__ b_hh1,
    const float* __restrict__ head_w1, const float* __restrict__ head_b1,
    const float* __restrict__ head_w2, const float* __restrict__ head_b2,
    const float* __restrict__ W_ih0, const float* __restrict__ W_hh0,
    const float* __restrict__ W_ih1, const float* __restrict__ W_hh1,
    float* __restrict__ y)
{
    extern __shared__ __align__(16) float sm[];
    const int tid   = threadIdx.x;
    const int kq    = tid & 3;
    const int u     = (tid >> 2) & 31;
    const int rq    = tid >> 7;
    const int crank = blockIdx.x & 3;
    const int b0    = (blockIdx.x >> 2) * RWS_;

    const int  tb   = u * 16 + kq * 4;
    const int  kqo  = kq * 4;
    const bool hiK  = kq & 2, hiP = kq & 1;
    const int  posu = (u >> 2) * 16 + crank * 4 + (u & 3);
    const int  rowb = rq * 8;

    // ---- one-time weight remap into SMEM ----
    for (int idx = tid; idx < 96 * KX_; idx += NTHR) {
        int g = idx / KX_, k = idx % KX_;
        int gt = g / 32, uu = g & 31;
        int kqq = k / 12, kk = (k % 12) >> 2, i = k & 3;
        sm[OFF_WIH0 + kk * 1536 + gt * 512 + uu * 16 + kqq * 4 + i] =
            W_ih0[(size_t)(gt * H_ + crank * UN_ + uu) * KX_ + k];
    }
    for (int idx = tid; idx < 96 * H_; idx += NTHR) {
        int g = idx / H_, k = idx % H_;
        int gt = g / 32, uu = g & 31;
        int kqq = k >> 5, kk = (k & 31) >> 2, i = k & 3;
        int dst = kk * 1536 + gt * 512 + uu * 16 + kqq * 4 + i;
        size_t grow = (size_t)(gt * H_ + crank * UN_ + uu);
        sm[OFF_WHH0 + dst] = W_hh0[grow * H_ + k];
        sm[OFF_WIH1 + dst] = W_ih1[grow * H_ + k];
        sm[OFF_WHH1 + dst] = W_hh1[grow * H_ + k];
    }
    for (int i = tid; i < 2 * RWS_ * H_; i += NTHR) sm[OFF_H0 + i] = 0.f;
    for (int i = tid; i < RWS_ * H_; i += NTHR)     sm[OFF_H1 + i] = 0.f;
    for (int idx = tid; idx < RWS_ * E_; idx += NTHR) {
        int r = idx >> 4, e = idx & 15, k = F_ + e;
        int kqq = k / 12, kk = (k % 12) >> 2, i = k & 3;
        sm[OFF_X + r * KX_ + kk * 16 + kqq * 4 + i] =
            embed[(size_t)ticker[b0 + r] * E_ + e];
    }
    if (tid < 256) {
        int r = tid >> 3, q = tid & 7;
        int kqq = q / 3, kk = q - 3 * kqq;
        *(float4*)&sm[OFF_X + r * KX_ + kk * 16 + kqq * 4] =
            *(const float4*)(x + ((size_t)(b0 + r) * T_) * F_ + q * 4);
    }
    const int jr = crank * UN_ + u;
    const float br0  = b_ih0[jr] + b_hh0[jr];
    const float bz0  = b_ih0[H_ + jr] + b_hh0[H_ + jr];
    const float bxn0 = b_ih0[2 * H_ + jr], bhn0 = b_hh0[2 * H_ + jr];
    const float br1  = b_ih1[jr] + b_hh1[jr];
    const float bz1  = b_ih1[H_ + jr] + b_hh1[H_ + jr];
    const float bxn1 = b_ih1[2 * H_ + jr], bhn1 = b_hh1[2 * H_ + jr];

    float h0own[2] = {0.f, 0.f};
    float h1own[2] = {0.f, 0.f};

    __syncthreads();
    CLUSTER_SYNC();

    float* xs  = sm + OFF_X;
    float* h1s = sm + OFF_H1;

    for (int t = 0; t < T_; ++t) {
        const float* h0cur = sm + OFF_H0 + (t & 1) * RWS_ * H_;
        float*       h0nxt = sm + OFF_H0 + ((t + 1) & 1) * RWS_ * H_;
        u64 A0[8], A1[8];
        float Rg[2], Zg[2], hA[2];

        // ---------- layer 0 (two passes) ----------
        accum_rz<3, KX_>(sm + OFF_WIH0, sm + OFF_WHH0,
                         xs + rowb * KX_, h0cur + rowb * H_, tb, kqo, A0, A1);
        finalize_rz(A0, A1, br0, bz0, hiK, hiP, Rg, Zg);
        accum_n<3, KX_>(sm + OFF_WIH0, sm + OFF_WHH0,
                        xs + rowb * KX_, h0cur + rowb * H_, tb, kqo, A0, A1);
        finalize_n(A0, A1, bxn0, bhn0, hiK, hiP, Rg, Zg, h0own, hA);
        {
            uint32_t base = smem_u32(h0nxt);
#pragma unroll
            for (int v2 = 0; v2 < 2; ++v2) {
                int row = rowb + 2 * kq + v2;
                uint32_t la = base + (uint32_t)(row * H_ + posu) * 4u;
#pragma unroll
                for (int rk = 0; rk < CL_; ++rk) st_cluster_f32(la, rk, hA[v2]);
            }
        }
        CLUSTER_SYNC();        // S1: h0(t) visible; x(t)/h0cur readers done

        if (t + 1 < T_ && tid < 256) {
            int r = tid >> 3, q = tid & 7;
            int kqq = q / 3, kk = q - 3 * kqq;
            *(float4*)&xs[r * KX_ + kk * 16 + kqq * 4] =
                *(const float4*)(x + ((size_t)(b0 + r) * T_ + t + 1) * F_ + q * 4);
        }

        // ---------- layer 1 (two passes) ----------
        accum_rz<8, H_>(sm + OFF_WIH1, sm + OFF_WHH1,
                        h0nxt + rowb * H_, h1s + rowb * H_, tb, kqo, A0, A1);
        finalize_rz(A0, A1, br1, bz1, hiK, hiP, Rg, Zg);
        accum_n<8, H_>(sm + OFF_WIH1, sm + OFF_WHH1,
                       h0nxt + rowb * H_, h1s + rowb * H_, tb, kqo, A0, A1);
        finalize_n(A0, A1, bxn1, bhn1, hiK, hiP, Rg, Zg, h1own, hA);
        CLUSTER_SYNC();        // S2: everyone finished READING h1(t-1)
        {
            uint32_t base = smem_u32(h1s);
#pragma unroll
            for (int v2 = 0; v2 < 2; ++v2) {
                int row = rowb + 2 * kq + v2;
                uint32_t la = base + (uint32_t)(row * H_ + posu) * 4u;
#pragma unroll
                for (int rk = 0; rk < CL_; ++rk) st_cluster_f32(la, rk, hA[v2]);
            }
        }
        CLUSTER_SYNC();        // S3: h1(t) visible
    }

    // ---------- head: rows [crank*8, crank*8+8) ----------
    float* scratch = xs;
    if (tid < H_) {
        const int uu = tid;
        const float w2  = head_w2[uu];
        const float b1v = head_b1[uu];
        float acc[8];
#pragma unroll
        for (int r = 0; r < 8; ++r) acc[r] = b1v;
#pragma unroll
        for (int kq4 = 0; kq4 < 4; ++kq4)
#pragma unroll
            for (int kk = 0; kk < 8; ++kk) {
                float4 w = *(const float4*)
                    (head_w1 + (size_t)uu * H_ + kq4 * 32 + kk * 4);
#pragma unroll
                for (int r = 0; r < 8; ++r) {
                    float4 v = *(const float4*)
                        &h1s[(crank * 8 + r) * H_ + kk * 16 + kq4 * 4];
                    acc[r] += w.x * v.x + w.y * v.y + w.z * v.z + w.w * v.w;
                }
            }
#pragma unroll
        for (int r = 0; r < 8; ++r)
            scratch[r * H_ + uu] = fmaxf(acc[r], 0.f) * w2;
    }
    __syncthreads();
    if (tid < 8) {
        float acc = head_b2[0];
        for (int k = 0; k < H_; ++k) acc += scratch[tid * H_ + k];
        y[b0 + crank * 8 + tid] = acc;
    }
}

extern "C" void kernel_launch(void* const* d_in, const int* in_sizes, int n_in,
                              void* d_out, int out_size) {
    const float* x       = (const float*)d_in[0];
    const int*   ticker  = (const int*)  d_in[1];
    const float* embed   = (const float*)d_in[2];
    const float* W_ih0   = (const float*)d_in[3];
    const float* W_hh0   = (const float*)d_in[4];
    const float* b_ih0   = (const float*)d_in[5];
    const float* b_hh0   = (const float*)d_in[6];
    const float* W_ih1   = (const float*)d_in[7];
    const float* W_hh1   = (const float*)d_in[8];
    const float* b_ih1   = (const float*)d_in[9];
    const float* b_hh1   = (const float*)d_in[10];
    const float* head_w1 = (const float*)d_in[11];
    const float* head_b1 = (const float*)d_in[12];
    const float* head_w2 = (const float*)d_in[13];
    const float* head_b2 = (const float*)d_in[14];

    cudaFuncSetAttribute(gru_kernel,
                         cudaFuncAttributeMaxDynamicSharedMemorySize, SMEM_BYTES);

    cudaLaunchConfig_t cfg = {};
    cfg.gridDim  = dim3(NCTA, 1, 1);
    cfg.blockDim = dim3(NTHR, 1, 1);
    cfg.dynamicSmemBytes = SMEM_BYTES;
    cfg.stream = 0;
    cudaLaunchAttribute attr[1];
    attr[0].id = cudaLaunchAttributeClusterDimension;
    attr[0].val.clusterDim.x = CL_;
    attr[0].val.clusterDim.y = 1;
    attr[0].val.clusterDim.z = 1;
    cfg.attrs = attr;
    cfg.numAttrs = 1;

    cudaLaunchKernelEx(&cfg, gru_kernel,
                       x, ticker, embed,
                       b_ih0, b_hh0, b_ih1, b_hh1,
                       head_w1, head_b1, head_w2, head_b2,
                       W_ih0, W_hh0, W_ih1, W_hh1,
                       (float*)d_out);
}

// round 11
// speedup vs baseline: 4.4815x; 4.4804x over previous
#include <cuda_runtime.h>
#include <cstdint>

#define T_    512
#define F_    32
#define E_    16
#define H_    128
#define KX_   48
#define CL_   4
#define UN_   32
#define RWS_  32
#define NCTA  128
#define NTHR  512   // tid = rq*128 + u*4 + kq

typedef unsigned long long u64;

#define OFF_WIH0 0
#define OFF_WHH0 (OFF_WIH0 + 3*1536)
#define OFF_WIH1 (OFF_WHH0 + 8*1536)
#define OFF_WHH1 (OFF_WIH1 + 8*1536)
#define OFF_H0   (OFF_WHH1 + 8*1536)
#define OFF_H1   (OFF_H0 + 2*RWS_*H_)
#define OFF_X    (OFF_H1 + RWS_*H_)
#define SMEM_FLOATS (OFF_X + RWS_*KX_)
#define SMEM_BYTES  (SMEM_FLOATS * 4)

__device__ __forceinline__ u64 fma2(u64 a, u64 b, u64 c) {
    u64 d;
    asm("fma.rn.f32x2 %0, %1, %2, %3;" : "=l"(d) : "l"(a), "l"(b), "l"(c));
    return d;
}
__device__ __forceinline__ float hsum2(u64 a) {
    float l, h;
    asm("mov.b64 {%0, %1}, %2;" : "=f"(l), "=f"(h) : "l"(a));
    return l + h;
}
__device__ __forceinline__ float sigmoidf_(float v) {
    return 1.f / (1.f + __expf(-v));
}
__device__ __forceinline__ float tanhf_(float v) {
    v = fminf(fmaxf(v, -15.f), 15.f);
    float e = __expf(2.f * v);
    return (e - 1.f) / (e + 1.f);
}
__device__ __forceinline__ uint32_t smem_u32(const void* p) {
    uint32_t a;
    asm("{ .reg .u64 t; cvta.to.shared.u64 t, %1; cvt.u32.u64 %0, t; }"
        : "=r"(a) : "l"(p));
    return a;
}
__device__ __forceinline__ void st_cluster_f32(uint32_t laddr, int rank, float v) {
    asm volatile(
        "{ .reg .b32 ra;\n\t"
        "mapa.shared::cluster.u32 ra, %0, %1;\n\t"
        "st.shared::cluster.f32 [ra], %2; }"
        :: "r"(laddr), "r"(rank), "f"(v) : "memory");
}
#define CARRIVE() asm volatile("barrier.cluster.arrive.aligned;" ::: "memory")
#define CWAIT()   asm volatile("barrier.cluster.wait.aligned;"   ::: "memory")

template<int NIH, int SIH>
__device__ __forceinline__ void block_accum(
    const float* __restrict__ Wih, const float* __restrict__ Whh,
    const float* __restrict__ vih, const float* __restrict__ vhh,
    int tb, int kqo,
    u64* __restrict__ Ar, u64* __restrict__ Az,
    u64* __restrict__ Ax, u64* __restrict__ Ah)
{
#pragma unroll
    for (int r = 0; r < 8; ++r) { Ar[r] = 0; Az[r] = 0; Ax[r] = 0; Ah[r] = 0; }
#pragma unroll
    for (int kk = 0; kk < NIH; ++kk) {
        const float* wp = Wih + kk * 1536 + tb;
        ulonglong2 wr = *(const ulonglong2*)wp;
        ulonglong2 wz = *(const ulonglong2*)(wp + 512);
        ulonglong2 wn = *(const ulonglong2*)(wp + 1024);
#pragma unroll
        for (int r = 0; r < 8; ++r) {
            ulonglong2 v = *(const ulonglong2*)(vih + r * SIH + kk * 16 + kqo);
            Ar[r] = fma2(wr.x, v.x, Ar[r]); Ar[r] = fma2(wr.y, v.y, Ar[r]);
            Az[r] = fma2(wz.x, v.x, Az[r]); Az[r] = fma2(wz.y, v.y, Az[r]);
            Ax[r] = fma2(wn.x, v.x, Ax[r]); Ax[r] = fma2(wn.y, v.y, Ax[r]);
        }
    }
#pragma unroll
    for (int kk = 0; kk < 8; ++kk) {
        const float* wp = Whh + kk * 1536 + tb;
        ulonglong2 wr = *(const ulonglong2*)wp;
        ulonglong2 wz = *(const ulonglong2*)(wp + 512);
        ulonglong2 wn = *(const ulonglong2*)(wp + 1024);
#pragma unroll
        for (int r = 0; r < 8; ++r) {
            ulonglong2 v = *(const ulonglong2*)(vhh + r * H_ + kk * 16 + kqo);
            Ar[r] = fma2(wr.x, v.x, Ar[r]); Ar[r] = fma2(wr.y, v.y, Ar[r]);
            Az[r] = fma2(wz.x, v.x, Az[r]); Az[r] = fma2(wz.y, v.y, Az[r]);
            Ah[r] = fma2(wn.x, v.x, Ah[r]); Ah[r] = fma2(wn.y, v.y, Ah[r]);
        }
    }
}

#define RED4(kout, s) \
    _Pragma("unroll") \
    for (int rr = 0; rr < 4; ++rr) { \
        float snd = hiK ? (s)[rr] : (s)[4 + rr]; \
        float kp  = hiK ? (s)[4 + rr] : (s)[rr]; \
        (kout)[rr] = kp + __shfl_xor_sync(0xffffffffu, snd, 2, 4); }
#define RED2(f, kin, rr) { \
        float snd = hiP ? (kin)[rr] : (kin)[2 + rr]; \
        float kp  = hiP ? (kin)[2 + rr] : (kin)[rr]; \
        f = kp + __shfl_xor_sync(0xffffffffu, snd, 1, 4); }

__device__ __forceinline__ void finalize2(
    const u64* Ar, const u64* Az, const u64* Ax, const u64* Ah,
    float br, float bz, float bxn, float bhn,
    bool hiK, bool hiP, float* hown, float* hout)
{
    float sr[8], sz[8], sx[8], sh[8];
#pragma unroll
    for (int r = 0; r < 8; ++r) {
        sr[r] = hsum2(Ar[r]); sz[r] = hsum2(Az[r]);
        sx[r] = hsum2(Ax[r]); sh[r] = hsum2(Ah[r]);
    }
    float kr[4], kz[4], kx[4], kh[4];
    RED4(kr, sr); RED4(kz, sz); RED4(kx, sx); RED4(kh, sh);
#pragma unroll
    for (int rr = 0; rr < 2; ++rr) {
        float fr, fz, fx, fh;
        RED2(fr, kr, rr); RED2(fz, kz, rr); RED2(fx, kx, rr); RED2(fh, kh, rr);
        float R = sigmoidf_(fr + br);
        float Z = sigmoidf_(fz + bz);
        float N = tanhf_(fx + bxn + R * (fh + bhn));
        float h = N + Z * (hown[rr] - N);
        hown[rr] = h;
        hout[rr] = h;
    }
}

__global__ void __launch_bounds__(NTHR, 1) gru_kernel(
    const float* __restrict__ x,
    const int*   __restrict__ ticker,
    const float* __restrict__ embed,
    const float* __restrict__ b_ih0, const float* __restrict__ b_hh0,
    const float* __restrict__ b_ih1, const float* __restrict__ b_hh1,
    const float* __restrict__ head_w1, const float* __restrict__ head_b1,
    const float* __restrict__ head_w2, const float* __restrict__ head_b2,
    const float* __restrict__ W_ih0, const float* __restrict__ W_hh0,
    const float* __restrict__ W_ih1, const float* __restrict__ W_hh1,
    float* __restrict__ y)
{
    extern __shared__ __align__(16) float sm[];
    const int tid   = threadIdx.x;
    const int kq    = tid & 3;
    const int u     = (tid >> 2) & 31;
    const int rq    = tid >> 7;
    const int crank = blockIdx.x & 3;
    const int b0    = (blockIdx.x >> 2) * RWS_;

    const int  tb   = u * 16 + kq * 4;
    const int  kqo  = kq * 4;
    const bool hiK  = kq & 2, hiP = kq & 1;
    const int  posu = (u >> 2) * 16 + crank * 4 + (u & 3);
    const int  rowb = rq * 8;

    for (int idx = tid; idx < 96 * KX_; idx += NTHR) {
        int g = idx / KX_, k = idx % KX_;
        int gt = g / 32, uu = g & 31;
        int kqq = k / 12, kk = (k % 12) >> 2, i = k & 3;
        sm[OFF_WIH0 + kk * 1536 + gt * 512 + uu * 16 + kqq * 4 + i] =
            W_ih0[(size_t)(gt * H_ + crank * UN_ + uu) * KX_ + k];
    }
    for (int idx = tid; idx < 96 * H_; idx += NTHR) {
        int g = idx / H_, k = idx % H_;
        int gt = g / 32, uu = g & 31;
        int kqq = k >> 5, kk = (k & 31) >> 2, i = k & 3;
        int dst = kk * 1536 + gt * 512 + uu * 16 + kqq * 4 + i;
        size_t grow = (size_t)(gt * H_ + crank * UN_ + uu);
        sm[OFF_WHH0 + dst] = W_hh0[grow * H_ + k];
        sm[OFF_WIH1 + dst] = W_ih1[grow * H_ + k];
        sm[OFF_WHH1 + dst] = W_hh1[grow * H_ + k];
    }
    for (int i = tid; i < 2 * RWS_ * H_; i += NTHR) sm[OFF_H0 + i] = 0.f;
    for (int i = tid; i < RWS_ * H_; i += NTHR)     sm[OFF_H1 + i] = 0.f;
    for (int idx = tid; idx < RWS_ * E_; idx += NTHR) {
        int r = idx >> 4, e = idx & 15, k = F_ + e;
        int kqq = k / 12, kk = (k % 12) >> 2, i = k & 3;
        sm[OFF_X + r * KX_ + kk * 16 + kqq * 4 + i] =
            embed[(size_t)ticker[b0 + r] * E_ + e];
    }
    if (tid < 256) {
        int r = tid >> 3, q = tid & 7;
        int kqq = q / 3, kk = q - 3 * kqq;
        *(float4*)&sm[OFF_X + r * KX_ + kk * 16 + kqq * 4] =
            *(const float4*)(x + ((size_t)(b0 + r) * T_) * F_ + q * 4);
    }
    const int jr = crank * UN_ + u;
    const float br0  = b_ih0[jr] + b_hh0[jr];
    const float bz0  = b_ih0[H_ + jr] + b_hh0[H_ + jr];
    const float bxn0 = b_ih0[2 * H_ + jr], bhn0 = b_hh0[2 * H_ + jr];
    const float br1  = b_ih1[jr] + b_hh1[jr];
    const float bz1  = b_ih1[H_ + jr] + b_hh1[H_ + jr];
    const float bxn1 = b_ih1[2 * H_ + jr], bhn1 = b_hh1[2 * H_ + jr];

    float h0own[2] = {0.f, 0.f};
    float h1own[2] = {0.f, 0.f};

    __syncthreads();
    CARRIVE(); CWAIT();        // full sync: weights/h/x visible
    CARRIVE();                 // prime: pairs with first in-loop CWAIT (S3')

    float* xs  = sm + OFF_X;
    float* h1s = sm + OFF_H1;

    for (int t = 0; t < T_; ++t) {
        const float* h0cur = sm + OFF_H0 + (t & 1) * RWS_ * H_;
        float*       h0nxt = sm + OFF_H0 + ((t + 1) & 1) * RWS_ * H_;
        u64 Ar[8], Az[8], Ax[8], Ah[8];
        float hA[2];

        // layer 0 accum (reads xs(t) [guarded S2(t-1)], h0cur [pre-S1(t-1)])
        block_accum<3, KX_>(sm + OFF_WIH0, sm + OFF_WHH0,
                            xs + rowb * KX_, h0cur + rowb * H_,
                            tb, kqo, Ar, Az, Ax, Ah);
        finalize2(Ar, Az, Ax, Ah, br0, bz0, bxn0, bhn0, hiK, hiP, h0own, hA);
        {   // publish h0(t): peers left this buffer before S1(t-1) -> safe
            uint32_t base = smem_u32(h0nxt);
#pragma unroll
            for (int v2 = 0; v2 < 2; ++v2) {
                int row = rowb + 2 * kq + v2;
                uint32_t la = base + (uint32_t)(row * H_ + posu) * 4u;
#pragma unroll
                for (int rk = 0; rk < CL_; ++rk) st_cluster_f32(la, rk, hA[v2]);
            }
        }
        CWAIT();               // S3(t-1): h1(t-1) now visible (deferred wait)
        CARRIVE();             // S1(t): my h0 publish + my xs/h0cur reads done
        CWAIT();               // S1(t): all h0(t) visible; xs free to restage

        if (t + 1 < T_ && tid < 256) {
            int r = tid >> 3, q = tid & 7;
            int kqq = q / 3, kk = q - 3 * kqq;
            *(float4*)&xs[r * KX_ + kk * 16 + kqq * 4] =
                *(const float4*)(x + ((size_t)(b0 + r) * T_ + t + 1) * F_ + q * 4);
        }

        // layer 1 accum (reads h0nxt [S1(t)], h1s(t-1) [S3(t-1) waited above])
        block_accum<8, H_>(sm + OFF_WIH1, sm + OFF_WHH1,
                           h0nxt + rowb * H_, h1s + rowb * H_,
                           tb, kqo, Ar, Az, Ax, Ah);
        CARRIVE();             // S2(t): my h1s reads done
        finalize2(Ar, Az, Ax, Ah, br1, bz1, bxn1, bhn1, hiK, hiP, h1own, hA);
        CWAIT();               // S2(t): ALL h1s reads done -> safe to overwrite
        {
            uint32_t base = smem_u32(h1s);
#pragma unroll
            for (int v2 = 0; v2 < 2; ++v2) {
                int row = rowb + 2 * kq + v2;
                uint32_t la = base + (uint32_t)(row * H_ + posu) * 4u;
#pragma unroll
                for (int rk = 0; rk < CL_; ++rk) st_cluster_f32(la, rk, hA[v2]);
            }
        }
        CARRIVE();             // S3(t): h1 publish issued (wait deferred)
    }
    CWAIT();                   // final S3: h1(T-1) visible for head

    float* scratch = xs;
    if (tid < H_) {
        const int uu = tid;
        const float w2  = head_w2[uu];
        const float b1v = head_b1[uu];
        float acc[8];
#pragma unroll
        for (int r = 0; r < 8; ++r) acc[r] = b1v;
#pragma unroll
        for (int kq4 = 0; kq4 < 4; ++kq4)
#pragma unroll
            for (int kk = 0; kk < 8; ++kk) {
                float4 w = *(const float4*)
                    (head_w1 + (size_t)uu * H_ + kq4 * 32 + kk * 4);
#pragma unroll
                for (int r = 0; r < 8; ++r) {
                    float4 v = *(const float4*)
                        &h1s[(crank * 8 + r) * H_ + kk * 16 + kq4 * 4];
                    acc[r] += w.x * v.x + w.y * v.y + w.z * v.z + w.w * v.w;
                }
            }
#pragma unroll
        for (int r = 0; r < 8; ++r)
            scratch[r * H_ + uu] = fmaxf(acc[r], 0.f) * w2;
    }
    __syncthreads();
    if (tid < 8) {
        float acc = head_b2[0];
        for (int k = 0; k < H_; ++k) acc += scratch[tid * H_ + k];
        y[b0 + crank * 8 + tid] = acc;
    }
}

extern "C" void kernel_launch(void* const* d_in, const int* in_sizes, int n_in,
                              void* d_out, int out_size) {
    const float* x       = (const float*)d_in[0];
    const int*   ticker  = (const int*)  d_in[1];
    const float* embed   = (const float*)d_in[2];
    const float* W_ih0   = (const float*)d_in[3];
    const float* W_hh0   = (const float*)d_in[4];
    const float* b_ih0   = (const float*)d_in[5];
    const float* b_hh0   = (const float*)d_in[6];
    const float* W_ih1   = (const float*)d_in[7];
    const float* W_hh1   = (const float*)d_in[8];
    const float* b_ih1   = (const float*)d_in[9];
    const float* b_hh1   = (const float*)d_in[10];
    const float* head_w1 = (const float*)d_in[11];
    const float* head_b1 = (const float*)d_in[12];
    const float* head_w2 = (const float*)d_in[13];
    const float* head_b2 = (const float*)d_in[14];

    cudaFuncSetAttribute(gru_kernel,
                         cudaFuncAttributeMaxDynamicSharedMemorySize, SMEM_BYTES);

    cudaLaunchConfig_t cfg = {};
    cfg.gridDim  = dim3(NCTA, 1, 1);
    cfg.blockDim = dim3(NTHR, 1, 1);
    cfg.dynamicSmemBytes = SMEM_BYTES;
    cfg.stream = 0;
    cudaLaunchAttribute attr[1];
    attr[0].id = cudaLaunchAttributeClusterDimension;
    attr[0].val.clusterDim.x = CL_;
    attr[0].val.clusterDim.y = 1;
    attr[0].val.clusterDim.z = 1;
    cfg.attrs = attr;
    cfg.numAttrs = 1;

    cudaLaunchKernelEx(&cfg, gru_kernel,
                       x, ticker, embed,
                       b_ih0, b_hh0, b_ih1, b_hh1,
                       head_w1, head_b1, head_w2, head_b2,
                       W_ih0, W_hh0, W_ih1, W_hh1,
                       (float*)d_out);
}

// round 12
// speedup vs baseline: 6.5207x; 1.4550x over previous
#include <cuda_runtime.h>
#include <cuda_bf16.h>
#include <cstdint>

#define T_   512
#define F_   32
#define E_   16
#define H_   128
#define CL_  4
#define UN_  32
#define RWS_ 32
#define NCTA 128
#define NTHR 256   // 8 warps: w = tid>>5, mt = w>>2, q = w&3

// uint4-unit offsets in dynamic SMEM
#define QB_HH0 0        // [q4][kt8][gt3][lane32] = 3072 uint4
#define QB_IH1 3072
#define QB_HH1 6144
#define QB_IH0 9216     // [q4][kt3][gt3][lane32] = 1152
#define QA_X   10368    // [mt2][kt3][h2][lane32] = 384
#define QA_H0  10752    // 2 bufs x [mt2][kt8][h2][lane32] = 2048
#define QA_H1  12800    // 1024
#define QSCR   13824    // 256 uint4 = 8x128 f32
#define SMEM_BYTES ((13824 + 256) * 16)

__device__ __forceinline__ float sigmoidf_(float v) {
    return 1.f / (1.f + __expf(-v));
}
__device__ __forceinline__ float tanhf_(float v) {
    v = fminf(fmaxf(v, -15.f), 15.f);
    float e = __expf(2.f * v);
    return (e - 1.f) / (e + 1.f);
}
__device__ __forceinline__ uint32_t smem_u32(const void* p) {
    uint32_t a;
    asm("{ .reg .u64 t; cvta.to.shared.u64 t, %1; cvt.u32.u64 %0, t; }"
        : "=r"(a) : "l"(p));
    return a;
}
__device__ __forceinline__ void stc_v2(uint32_t la, int rk, uint32_t a, uint32_t b) {
    asm volatile(
        "{ .reg .b32 ra;\n\t"
        "mapa.shared::cluster.u32 ra, %0, %1;\n\t"
        "st.shared::cluster.v2.b32 [ra], {%2, %3}; }"
        :: "r"(la), "r"(rk), "r"(a), "r"(b) : "memory");
}
__device__ __forceinline__ void stc_f32(uint32_t la, int rk, float v) {
    asm volatile(
        "{ .reg .b32 ra;\n\t"
        "mapa.shared::cluster.u32 ra, %0, %1;\n\t"
        "st.shared::cluster.f32 [ra], %2; }"
        :: "r"(la), "r"(rk), "f"(v) : "memory");
}
#define CARRIVE() asm volatile("barrier.cluster.arrive.aligned;" ::: "memory")
#define CWAIT()   asm volatile("barrier.cluster.wait.aligned;"   ::: "memory")

__device__ __forceinline__ void mma4(float* d, uint32_t a0, uint32_t a1,
                                     uint32_t a2, uint32_t a3,
                                     uint32_t b0, uint32_t b1) {
    asm("mma.sync.aligned.m16n8k16.row.col.f32.bf16.bf16.f32 "
        "{%0,%1,%2,%3},{%4,%5,%6,%7},{%8,%9},{%0,%1,%2,%3};"
        : "+f"(d[0]), "+f"(d[1]), "+f"(d[2]), "+f"(d[3])
        : "r"(a0), "r"(a1), "r"(a2), "r"(a3), "r"(b0), "r"(b1));
}

// one operand matrix: KT ktiles, 3 gates (r,z,n->Dn), bf16x3 passes
template<int KT>
__device__ __forceinline__ void mma_mat(const uint4* B, const uint4* A, int lane,
                                        float* Dr, float* Dz, float* Dn) {
#pragma unroll
    for (int kt = 0; kt < KT; ++kt) {
        uint4 s0 = A[(kt * 2 + 0) * 32 + lane];   // {a0h,a1h,a0l,a1l}
        uint4 s1 = A[(kt * 2 + 1) * 32 + lane];   // {a2h,a3h,a2l,a3l}
#pragma unroll
        for (int gt = 0; gt < 3; ++gt) {
            uint4 b = B[(kt * 3 + gt) * 32 + lane];  // {b0h,b1h,b0l,b1l}
            float* D = (gt == 0) ? Dr : (gt == 1) ? Dz : Dn;
            mma4(D, s0.x, s0.y, s1.x, s1.y, b.x, b.y);  // ah*bh
            mma4(D, s0.z, s0.w, s1.z, s1.w, b.x, b.y);  // al*bh
            mma4(D, s0.x, s0.y, s1.x, s1.y, b.z, b.w);  // ah*bl
        }
    }
}

__device__ __forceinline__ void split2(float f0, float f1,
                                       uint32_t& hi, uint32_t& lo) {
    __nv_bfloat162 h = __floats2bfloat162_rn(f0, f1);   // .x=f0(low),.y=f1
    float r0 = f0 - __bfloat162float(h.x);
    float r1 = f1 - __bfloat162float(h.y);
    __nv_bfloat162 l = __floats2bfloat162_rn(r0, r1);
    hi = *reinterpret_cast<uint32_t*>(&h);
    lo = *reinterpret_cast<uint32_t*>(&l);
}
__device__ __forceinline__ void wsplit(uint4* slotp, int boff, float w) {
    __nv_bfloat16 h = __float2bfloat16(w);
    __nv_bfloat16 l = __float2bfloat16(w - __bfloat162float(h));
    char* p = (char*)slotp;
    *(__nv_bfloat16*)(p + boff)     = h;
    *(__nv_bfloat16*)(p + 8 + boff) = l;
}

__global__ void __launch_bounds__(NTHR, 1) gru_kernel(
    const float* __restrict__ x,
    const int*   __restrict__ ticker,
    const float* __restrict__ embed,
    const float* __restrict__ b_ih0, const float* __restrict__ b_hh0,
    const float* __restrict__ b_ih1, const float* __restrict__ b_hh1,
    const float* __restrict__ head_w1, const float* __restrict__ head_b1,
    const float* __restrict__ head_w2, const float* __restrict__ head_b2,
    const float* __restrict__ W_ih0, const float* __restrict__ W_hh0,
    const float* __restrict__ W_ih1, const float* __restrict__ W_hh1,
    float* __restrict__ y)
{
    extern __shared__ __align__(16) uint4 smq[];
    const int tid   = threadIdx.x;
    const int lane  = tid & 31;
    const int w     = tid >> 5;
    const int mt    = w >> 2;            // m-tile (rows mt*16..+16)
    const int q     = w & 3;             // n-quad (units q*8..+8 local)
    const int gid   = lane >> 2;
    const int tig   = lane & 3;
    const int crank = blockIdx.x & 3;
    const int b0    = (blockIdx.x >> 2) * RWS_;

    // ---- weight remap: fp32 -> fragment-direct bf16 hi/lo ----
    for (int idx = tid; idx < 96 * H_; idx += NTHR) {
        int g = idx >> 7, k = idx & 127;
        int gt = g >> 5, ul = g & 31;
        int qq = ul >> 3, gidn = ul & 7;
        int kt = k >> 4, klo = k & 15;
        int boff = ((klo >> 3) & 1) * 4 + (klo & 1) * 2;
        int slot = ((qq * 8 + kt) * 3 + gt) * 32 + gidn * 4 + ((klo >> 1) & 3);
        size_t grow = (size_t)(gt * H_ + crank * UN_ + ul);
        wsplit(smq + QB_HH0 + slot, boff, W_hh0[grow * H_ + k]);
        wsplit(smq + QB_IH1 + slot, boff, W_ih1[grow * H_ + k]);
        wsplit(smq + QB_HH1 + slot, boff, W_hh1[grow * H_ + k]);
    }
    for (int idx = tid; idx < 96 * 48; idx += NTHR) {
        int g = idx / 48, k = idx % 48;
        int gt = g >> 5, ul = g & 31;
        int qq = ul >> 3, gidn = ul & 7;
        int kt = k >> 4, klo = k & 15;
        int boff = ((klo >> 3) & 1) * 4 + (klo & 1) * 2;
        int slot = ((qq * 3 + kt) * 3 + gt) * 32 + gidn * 4 + ((klo >> 1) & 3);
        size_t grow = (size_t)(gt * H_ + crank * UN_ + ul);
        wsplit(smq + QB_IH0 + slot, boff, W_ih0[grow * 48 + k]);
    }
    // zero h planes (3072 uint4 = 12288 u32)
    for (int i = tid; i < 12288; i += NTHR)
        ((uint32_t*)(smq + QA_H0))[i] = 0;

    // embed into x-plane kt=2 (constant across t)
    {
        int r = tid >> 3, kp = 16 + (tid & 7);
        int e0 = 2 * kp - 32;
        float f0 = embed[(size_t)ticker[b0 + r] * E_ + e0];
        float f1 = embed[(size_t)ticker[b0 + r] * E_ + e0 + 1];
        int mtt = r >> 4, rl = r & 15;
        int ln = (rl & 7) * 4 + (kp & 3), h2 = (kp >> 2) & 1, kt = kp >> 3;
        uint4* sp = smq + QA_X + ((mtt * 3 + kt) * 2 + h2) * 32 + ln;
        uint32_t hi, lo; split2(f0, f1, hi, lo);
        ((uint32_t*)sp)[rl >> 3] = hi;
        ((uint32_t*)sp)[2 + (rl >> 3)] = lo;
    }
    // x(t=0)
#pragma unroll
    for (int s = 0; s < 2; ++s) {
        int p2 = tid * 2 + s;
        int r = p2 >> 4, kp = p2 & 15;
        float2 v = *(const float2*)(x + ((size_t)(b0 + r) * T_) * F_ + 2 * kp);
        int mtt = r >> 4, rl = r & 15;
        int ln = (rl & 7) * 4 + (kp & 3), h2 = (kp >> 2) & 1, kt = kp >> 3;
        uint4* sp = smq + QA_X + ((mtt * 3 + kt) * 2 + h2) * 32 + ln;
        uint32_t hi, lo; split2(v.x, v.y, hi, lo);
        ((uint32_t*)sp)[rl >> 3] = hi;
        ((uint32_t*)sp)[2 + (rl >> 3)] = lo;
    }
    // biases for my 2 units
    const int ug0 = crank * 32 + q * 8 + 2 * tig;
    float br0b[2], bz0b[2], bxn0b[2], bhn0b[2];
    float br1b[2], bz1b[2], bxn1b[2], bhn1b[2];
#pragma unroll
    for (int e = 0; e < 2; ++e) {
        int j = ug0 + e;
        br0b[e]  = b_ih0[j] + b_hh0[j];
        bz0b[e]  = b_ih0[H_ + j] + b_hh0[H_ + j];
        bxn0b[e] = b_ih0[2 * H_ + j];
        bhn0b[e] = b_hh0[2 * H_ + j];
        br1b[e]  = b_ih1[j] + b_hh1[j];
        bz1b[e]  = b_ih1[H_ + j] + b_hh1[H_ + j];
        bxn1b[e] = b_ih1[2 * H_ + j];
        bhn1b[e] = b_hh1[2 * H_ + j];
    }
    float h0own[4] = {0.f, 0.f, 0.f, 0.f};
    float h1own[4] = {0.f, 0.f, 0.f, 0.f};

    const int pkt = crank * 2 + (q >> 1);      // publish ktile
    const int ph2 = q & 1;                     // publish half2
    const uint32_t poff = (uint32_t)(((mt * 8 + pkt) * 2 + ph2) * 32 + lane) * 16u;

    __syncthreads();
    CARRIVE(); CWAIT();        // full sync: weights/planes visible
    CARRIVE();                 // prime S3'

#pragma unroll 1
    for (int t = 0; t < T_; ++t) {
        const uint4* AH0c = smq + QA_H0 + (t & 1) * 1024 + mt * 512;
        const uint4* AH0n = smq + QA_H0 + ((t + 1) & 1) * 1024 + mt * 512;
        uint4* AH0n_pl    = smq + QA_H0 + ((t + 1) & 1) * 1024;
        float Dr[4] = {0,0,0,0}, Dz[4] = {0,0,0,0};
        float Dnx[4] = {0,0,0,0}, Dnh[4] = {0,0,0,0};
        float hv[4];

        // ---- layer 0 ----
        mma_mat<3>(smq + QB_IH0 + q * 288, smq + QA_X + mt * 192, lane, Dr, Dz, Dnx);
        mma_mat<8>(smq + QB_HH0 + q * 768, AH0c, lane, Dr, Dz, Dnh);
#pragma unroll
        for (int e = 0; e < 4; ++e) {
            float R = sigmoidf_(Dr[e] + br0b[e & 1]);
            float Z = sigmoidf_(Dz[e] + bz0b[e & 1]);
            float N = tanhf_(Dnx[e] + bxn0b[e & 1] + R * (Dnh[e] + bhn0b[e & 1]));
            hv[e] = N + Z * (h0own[e] - N);
            h0own[e] = hv[e];
        }
        {   // publish h0(t) to all ranks' next-buffer planes
            uint32_t a0h, a0l, a1h, a1l;
            split2(hv[0], hv[1], a0h, a0l);
            split2(hv[2], hv[3], a1h, a1l);
            uint32_t la = smem_u32(AH0n_pl) + poff;
#pragma unroll
            for (int rk = 0; rk < CL_; ++rk) {
                stc_v2(la, rk, a0h, a1h);
                stc_v2(la + 8, rk, a0l, a1l);
            }
        }
        CWAIT();               // S3(t-1): h1(t-1) visible
        CARRIVE();             // S1(t)
        CWAIT();               // S1(t): all h0(t) visible; x restage safe

        if (t + 1 < T_) {
#pragma unroll
            for (int s = 0; s < 2; ++s) {
                int p2 = tid * 2 + s;
                int r = p2 >> 4, kp = p2 & 15;
                float2 v = *(const float2*)
                    (x + ((size_t)(b0 + r) * T_ + t + 1) * F_ + 2 * kp);
                int mtt = r >> 4, rl = r & 15;
                int ln = (rl & 7) * 4 + (kp & 3), h2 = (kp >> 2) & 1, kt = kp >> 3;
                uint4* sp = smq + QA_X + ((mtt * 3 + kt) * 2 + h2) * 32 + ln;
                uint32_t hi, lo; split2(v.x, v.y, hi, lo);
                ((uint32_t*)sp)[rl >> 3] = hi;
                ((uint32_t*)sp)[2 + (rl >> 3)] = lo;
            }
        }

        // ---- layer 1 ----
#pragma unroll
        for (int e = 0; e < 4; ++e) { Dr[e] = 0; Dz[e] = 0; Dnx[e] = 0; Dnh[e] = 0; }
        mma_mat<8>(smq + QB_IH1 + q * 768, AH0n, lane, Dr, Dz, Dnx);
        mma_mat<8>(smq + QB_HH1 + q * 768, smq + QA_H1 + mt * 512, lane, Dr, Dz, Dnh);
        CARRIVE();             // S2(t): my h1 reads done
#pragma unroll
        for (int e = 0; e < 4; ++e) {
            float R = sigmoidf_(Dr[e] + br1b[e & 1]);
            float Z = sigmoidf_(Dz[e] + bz1b[e & 1]);
            float N = tanhf_(Dnx[e] + bxn1b[e & 1] + R * (Dnh[e] + bhn1b[e & 1]));
            hv[e] = N + Z * (h1own[e] - N);
            h1own[e] = hv[e];
        }
        CWAIT();               // S2(t): all h1 reads done -> overwrite safe
        {
            uint32_t a0h, a0l, a1h, a1l;
            split2(hv[0], hv[1], a0h, a0l);
            split2(hv[2], hv[3], a1h, a1l);
            uint32_t la = smem_u32(smq + QA_H1) + poff;
#pragma unroll
            for (int rk = 0; rk < CL_; ++rk) {
                stc_v2(la, rk, a0h, a1h);
                stc_v2(la + 8, rk, a0l, a1l);
            }
        }
        if (t == T_ - 1) {     // fp32 h1 -> owner rank's scratch for head
            float* scr = (float*)(smq + QSCR);
#pragma unroll
            for (int e = 0; e < 4; ++e) {
                int row = mt * 16 + gid + (e >> 1) * 8;
                int ug  = ug0 + (e & 1);
                uint32_t la = smem_u32(scr + (row & 7) * H_ + ug);
                stc_f32(la, row >> 3, hv[e]);
            }
        }
        CARRIVE();             // S3(t)
    }
    CWAIT();                   // final: scratch + h1 visible

    // ---- head: rows [crank*8, crank*8+8) from fp32 scratch ----
    const float* scr = (const float*)(smq + QSCR);
    float* hid = (float*)(smq + QA_X);   // reuse as 8x128 scratch
    if (tid < H_) {
        const float w2  = head_w2[tid];
        const float b1v = head_b1[tid];
        float acc[8];
#pragma unroll
        for (int r = 0; r < 8; ++r) acc[r] = b1v;
        for (int k4 = 0; k4 < 32; ++k4) {
            float4 wv = *(const float4*)(head_w1 + (size_t)tid * H_ + k4 * 4);
#pragma unroll
            for (int r = 0; r < 8; ++r) {
                float4 v = *(const float4*)(scr + r * H_ + k4 * 4);
                acc[r] += wv.x * v.x + wv.y * v.y + wv.z * v.z + wv.w * v.w;
            }
        }
#pragma unroll
        for (int r = 0; r < 8; ++r)
            hid[r * H_ + tid] = fmaxf(acc[r], 0.f) * w2;
    }
    __syncthreads();
    if (tid < 8) {
        float acc = head_b2[0];
        for (int k = 0; k < H_; ++k) acc += hid[tid * H_ + k];
        y[b0 + crank * 8 + tid] = acc;
    }
}

extern "C" void kernel_launch(void* const* d_in, const int* in_sizes, int n_in,
                              void* d_out, int out_size) {
    const float* x       = (const float*)d_in[0];
    const int*   ticker  = (const int*)  d_in[1];
    const float* embed   = (const float*)d_in[2];
    const float* W_ih0   = (const float*)d_in[3];
    const float* W_hh0   = (const float*)d_in[4];
    const float* b_ih0   = (const float*)d_in[5];
    const float* b_hh0   = (const float*)d_in[6];
    const float* W_ih1   = (const float*)d_in[7];
    const float* W_hh1   = (const float*)d_in[8];
    const float* b_ih1   = (const float*)d_in[9];
    const float* b_hh1   = (const float*)d_in[10];
    const float* head_w1 = (const float*)d_in[11];
    const float* head_b1 = (const float*)d_in[12];
    const float* head_w2 = (const float*)d_in[13];
    const float* head_b2 = (const float*)d_in[14];

    cudaFuncSetAttribute(gru_kernel,
                         cudaFuncAttributeMaxDynamicSharedMemorySize, SMEM_BYTES);

    cudaLaunchConfig_t cfg = {};
    cfg.gridDim  = dim3(NCTA, 1, 1);
    cfg.blockDim = dim3(NTHR, 1, 1);
    cfg.dynamicSmemBytes = SMEM_BYTES;
    cfg.stream = 0;
    cudaLaunchAttribute attr[1];
    attr[0].id = cudaLaunchAttributeClusterDimension;
    attr[0].val.clusterDim.x = CL_;
    attr[0].val.clusterDim.y = 1;
    attr[0].val.clusterDim.z = 1;
    cfg.attrs = attr;
    cfg.numAttrs = 1;

    cudaLaunchKernelEx(&cfg, gru_kernel,
                       x, ticker, embed,
                       b_ih0, b_hh0, b_ih1, b_hh1,
                       head_w1, head_b1, head_w2, head_b2,
                       W_ih0, W_hh0, W_ih1, W_hh1,
                       (float*)d_out);
}

// round 13
// speedup vs baseline: 9.3620x; 1.4357x over previous
#include <cuda_runtime.h>
#include <cuda_bf16.h>
#include <cstdint>

#define T_   512
#define F_   32
#define E_   16
#define H_   128
#define CL_  4
#define UN_  32
#define RWS_ 32
#define NCTA 128
#define NTHR 256

#define QB_HH0 0
#define QB_IH1 3072
#define QB_HH1 6144
#define QB_IH0 9216
#define QA_X   10368
#define QA_H0  10752
#define QA_H1  12800
#define QSCR   13824
#define SMEM_BYTES ((13824 + 256) * 16)

__device__ __forceinline__ float sigmoidf_(float v) {
    return 1.f / (1.f + __expf(-v));
}
__device__ __forceinline__ float tanhf_(float v) {
    v = fminf(fmaxf(v, -15.f), 15.f);
    float e = __expf(2.f * v);
    return (e - 1.f) / (e + 1.f);
}
__device__ __forceinline__ uint32_t smem_u32(const void* p) {
    uint32_t a;
    asm("{ .reg .u64 t; cvta.to.shared.u64 t, %1; cvt.u32.u64 %0, t; }"
        : "=r"(a) : "l"(p));
    return a;
}
__device__ __forceinline__ void stc_v4(uint32_t la, int rk, uint32_t a,
                                       uint32_t b, uint32_t c, uint32_t d) {
    asm volatile(
        "{ .reg .b32 ra;\n\t"
        "mapa.shared::cluster.u32 ra, %0, %1;\n\t"
        "st.shared::cluster.v4.b32 [ra], {%2, %3, %4, %5}; }"
        :: "r"(la), "r"(rk), "r"(a), "r"(b), "r"(c), "r"(d) : "memory");
}
__device__ __forceinline__ void stc_f32(uint32_t la, int rk, float v) {
    asm volatile(
        "{ .reg .b32 ra;\n\t"
        "mapa.shared::cluster.u32 ra, %0, %1;\n\t"
        "st.shared::cluster.f32 [ra], %2; }"
        :: "r"(la), "r"(rk), "f"(v) : "memory");
}
#define CARRIVE() asm volatile("barrier.cluster.arrive.aligned;" ::: "memory")
#define CWAIT()   asm volatile("barrier.cluster.wait.aligned;"   ::: "memory")

__device__ __forceinline__ void mma4(float* d, uint32_t a0, uint32_t a1,
                                     uint32_t a2, uint32_t a3,
                                     uint32_t b0, uint32_t b1) {
    asm("mma.sync.aligned.m16n8k16.row.col.f32.bf16.bf16.f32 "
        "{%0,%1,%2,%3},{%4,%5,%6,%7},{%8,%9},{%0,%1,%2,%3};"
        : "+f"(d[0]), "+f"(d[1]), "+f"(d[2]), "+f"(d[3])
        : "r"(a0), "r"(a1), "r"(a2), "r"(a3), "r"(b0), "r"(b1));
}

template<int KT>
__device__ __forceinline__ void mma_mat(const uint4* B, const uint4* A, int lane,
                                        float* Dr, float* Dz, float* Dn) {
#pragma unroll
    for (int kt = 0; kt < KT; ++kt) {
        uint4 s0 = A[(kt * 2 + 0) * 32 + lane];
        uint4 s1 = A[(kt * 2 + 1) * 32 + lane];
#pragma unroll
        for (int gt = 0; gt < 3; ++gt) {
            uint4 b = B[(kt * 3 + gt) * 32 + lane];
            float* D = (gt == 0) ? Dr : (gt == 1) ? Dz : Dn;
            mma4(D, s0.x, s0.y, s1.x, s1.y, b.x, b.y);
            mma4(D, s0.z, s0.w, s1.z, s1.w, b.x, b.y);
            mma4(D, s0.x, s0.y, s1.x, s1.y, b.z, b.w);
        }
    }
}

__device__ __forceinline__ void split2(float f0, float f1,
                                       uint32_t& hi, uint32_t& lo) {
    __nv_bfloat162 h = __floats2bfloat162_rn(f0, f1);
    float r0 = f0 - __bfloat162float(h.x);
    float r1 = f1 - __bfloat162float(h.y);
    __nv_bfloat162 l = __floats2bfloat162_rn(r0, r1);
    hi = *reinterpret_cast<uint32_t*>(&h);
    lo = *reinterpret_cast<uint32_t*>(&l);
}
__device__ __forceinline__ void wsplit(uint4* slotp, int boff, float w) {
    __nv_bfloat16 h = __float2bfloat16(w);
    __nv_bfloat16 l = __float2bfloat16(w - __bfloat162float(h));
    char* p = (char*)slotp;
    *(__nv_bfloat16*)(p + boff)     = h;
    *(__nv_bfloat16*)(p + 8 + boff) = l;
}

__global__ void __launch_bounds__(NTHR, 1) gru_kernel(
    const float* __restrict__ x,
    const int*   __restrict__ ticker,
    const float* __restrict__ embed,
    const float* __restrict__ b_ih0, const float* __restrict__ b_hh0,
    const float* __restrict__ b_ih1, const float* __restrict__ b_hh1,
    const float* __restrict__ head_w1, const float* __restrict__ head_b1,
    const float* __restrict__ head_w2, const float* __restrict__ head_b2,
    const float* __restrict__ W_ih0, const float* __restrict__ W_hh0,
    const float* __restrict__ W_ih1, const float* __restrict__ W_hh1,
    float* __restrict__ y)
{
    extern __shared__ __align__(16) uint4 smq[];
    const int tid   = threadIdx.x;
    const int lane  = tid & 31;
    const int w     = tid >> 5;
    const int mt    = w >> 2;
    const int q     = w & 3;
    const int gid   = lane >> 2;
    const int tig   = lane & 3;
    const int crank = blockIdx.x & 3;
    const int b0    = (blockIdx.x >> 2) * RWS_;

    // ---- weight remap: fp32 -> fragment-direct bf16 hi/lo ----
    for (int idx = tid; idx < 96 * H_; idx += NTHR) {
        int g = idx >> 7, k = idx & 127;
        int gt = g >> 5, ul = g & 31;
        int qq = ul >> 3, gidn = ul & 7;
        int kt = k >> 4, klo = k & 15;
        int boff = ((klo >> 3) & 1) * 4 + (klo & 1) * 2;
        int slot = ((qq * 8 + kt) * 3 + gt) * 32 + gidn * 4 + ((klo >> 1) & 3);
        size_t grow = (size_t)(gt * H_ + crank * UN_ + ul);
        wsplit(smq + QB_HH0 + slot, boff, W_hh0[grow * H_ + k]);
        wsplit(smq + QB_IH1 + slot, boff, W_ih1[grow * H_ + k]);
        wsplit(smq + QB_HH1 + slot, boff, W_hh1[grow * H_ + k]);
    }
    for (int idx = tid; idx < 96 * 48; idx += NTHR) {
        int g = idx / 48, k = idx % 48;
        int gt = g >> 5, ul = g & 31;
        int qq = ul >> 3, gidn = ul & 7;
        int kt = k >> 4, klo = k & 15;
        int boff = ((klo >> 3) & 1) * 4 + (klo & 1) * 2;
        int slot = ((qq * 3 + kt) * 3 + gt) * 32 + gidn * 4 + ((klo >> 1) & 3);
        size_t grow = (size_t)(gt * H_ + crank * UN_ + ul);
        wsplit(smq + QB_IH0 + slot, boff, W_ih0[grow * 48 + k]);
    }
    for (int i = tid; i < 12288; i += NTHR)
        ((uint32_t*)(smq + QA_H0))[i] = 0;

    {   // embed into x-plane kt=2 (constant)
        int r = tid >> 3, kp = 16 + (tid & 7);
        int e0 = 2 * kp - 32;
        float f0 = embed[(size_t)ticker[b0 + r] * E_ + e0];
        float f1 = embed[(size_t)ticker[b0 + r] * E_ + e0 + 1];
        int mtt = r >> 4, rl = r & 15;
        int ln = (rl & 7) * 4 + (kp & 3), h2 = (kp >> 2) & 1, kt = kp >> 3;
        uint4* sp = smq + QA_X + ((mtt * 3 + kt) * 2 + h2) * 32 + ln;
        uint32_t hi, lo; split2(f0, f1, hi, lo);
        ((uint32_t*)sp)[rl >> 3] = hi;
        ((uint32_t*)sp)[2 + (rl >> 3)] = lo;
    }
#pragma unroll
    for (int s = 0; s < 2; ++s) {   // x(t=0)
        int p2 = tid * 2 + s;
        int r = p2 >> 4, kp = p2 & 15;
        float2 v = *(const float2*)(x + ((size_t)(b0 + r) * T_) * F_ + 2 * kp);
        int mtt = r >> 4, rl = r & 15;
        int ln = (rl & 7) * 4 + (kp & 3), h2 = (kp >> 2) & 1, kt = kp >> 3;
        uint4* sp = smq + QA_X + ((mtt * 3 + kt) * 2 + h2) * 32 + ln;
        uint32_t hi, lo; split2(v.x, v.y, hi, lo);
        ((uint32_t*)sp)[rl >> 3] = hi;
        ((uint32_t*)sp)[2 + (rl >> 3)] = lo;
    }
    const int ug0 = crank * 32 + q * 8 + 2 * tig;
    float br0b[2], bz0b[2], bxn0b[2], bhn0b[2];
    float br1b[2], bz1b[2], bxn1b[2], bhn1b[2];
#pragma unroll
    for (int e = 0; e < 2; ++e) {
        int j = ug0 + e;
        br0b[e]  = b_ih0[j] + b_hh0[j];
        bz0b[e]  = b_ih0[H_ + j] + b_hh0[H_ + j];
        bxn0b[e] = b_ih0[2 * H_ + j];
        bhn0b[e] = b_hh0[2 * H_ + j];
        br1b[e]  = b_ih1[j] + b_hh1[j];
        bz1b[e]  = b_ih1[H_ + j] + b_hh1[H_ + j];
        bxn1b[e] = b_ih1[2 * H_ + j];
        bhn1b[e] = b_hh1[2 * H_ + j];
    }
    float h0own[4] = {0.f, 0.f, 0.f, 0.f};
    float h1own[4] = {0.f, 0.f, 0.f, 0.f};

    const int pkt = crank * 2 + (q >> 1);
    const int ph2 = q & 1;
    const uint32_t poff = (uint32_t)(((mt * 8 + pkt) * 2 + ph2) * 32 + lane) * 16u;

    __syncthreads();
    CARRIVE(); CWAIT();
    CARRIVE();                 // prime S3'

#pragma unroll 1
    for (int t = 0; t < T_; ++t) {
        const uint4* AH0c = smq + QA_H0 + (t & 1) * 1024 + mt * 512;
        const uint4* AH0n = smq + QA_H0 + ((t + 1) & 1) * 1024 + mt * 512;
        uint4* AH0n_pl    = smq + QA_H0 + ((t + 1) & 1) * 1024;
        float Dr0[4] = {0,0,0,0}, Dz0[4] = {0,0,0,0}, Dnx[4] = {0,0,0,0};
        float Dr1[4] = {0,0,0,0}, Dz1[4] = {0,0,0,0}, Dnh[4] = {0,0,0,0};
        float hv[4];

        // ---- layer 0 (independent accumulator sets per matrix) ----
        mma_mat<3>(smq + QB_IH0 + q * 288, smq + QA_X + mt * 192, lane,
                   Dr0, Dz0, Dnx);
        mma_mat<8>(smq + QB_HH0 + q * 768, AH0c, lane, Dr1, Dz1, Dnh);
#pragma unroll
        for (int e = 0; e < 4; ++e) {
            float R = sigmoidf_(Dr0[e] + Dr1[e] + br0b[e & 1]);
            float Z = sigmoidf_(Dz0[e] + Dz1[e] + bz0b[e & 1]);
            float N = tanhf_(Dnx[e] + bxn0b[e & 1] + R * (Dnh[e] + bhn0b[e & 1]));
            hv[e] = N + Z * (h0own[e] - N);
            h0own[e] = hv[e];
        }
        {   // publish h0(t): single v4 store per rank
            uint32_t a0h, a0l, a1h, a1l;
            split2(hv[0], hv[1], a0h, a0l);
            split2(hv[2], hv[3], a1h, a1l);
            uint32_t la = smem_u32(AH0n_pl) + poff;
#pragma unroll
            for (int rk = 0; rk < CL_; ++rk)
                stc_v4(la, rk, a0h, a1h, a0l, a1l);
        }
        CWAIT();               // S3(t-1): h1(t-1) visible (deferred)
        CARRIVE();             // S1(t): h0 publish issued
        __syncthreads();       // CTA-local: all warps done reading xs(t)

        if (t + 1 < T_) {      // restage x(t+1) (CTA-local; legal pre-S1.wait)
#pragma unroll
            for (int s = 0; s < 2; ++s) {
                int p2 = tid * 2 + s;
                int r = p2 >> 4, kp = p2 & 15;
                float2 v = *(const float2*)
                    (x + ((size_t)(b0 + r) * T_ + t + 1) * F_ + 2 * kp);
                int mtt = r >> 4, rl = r & 15;
                int ln = (rl & 7) * 4 + (kp & 3), h2 = (kp >> 2) & 1, kt = kp >> 3;
                uint4* sp = smq + QA_X + ((mtt * 3 + kt) * 2 + h2) * 32 + ln;
                uint32_t hi, lo; split2(v.x, v.y, hi, lo);
                ((uint32_t*)sp)[rl >> 3] = hi;
                ((uint32_t*)sp)[2 + (rl >> 3)] = lo;
            }
        }

        // ---- layer 1 hh-part (reads h1s(t-1): S3 waited) — hides S1 drain ----
#pragma unroll
        for (int e = 0; e < 4; ++e) { Dr1[e] = 0; Dz1[e] = 0; Dnh[e] = 0; }
        mma_mat<8>(smq + QB_HH1 + q * 768, smq + QA_H1 + mt * 512, lane,
                   Dr1, Dz1, Dnh);
        CWAIT();               // S1(t): all h0(t) visible
        // ---- layer 1 ih-part (reads h0(t)) ----
#pragma unroll
        for (int e = 0; e < 4; ++e) { Dr0[e] = 0; Dz0[e] = 0; Dnx[e] = 0; }
        mma_mat<8>(smq + QB_IH1 + q * 768, AH0n, lane, Dr0, Dz0, Dnx);
        CARRIVE();             // S2(t): my h1s reads done
#pragma unroll
        for (int e = 0; e < 4; ++e) {
            float R = sigmoidf_(Dr0[e] + Dr1[e] + br1b[e & 1]);
            float Z = sigmoidf_(Dz0[e] + Dz1[e] + bz1b[e & 1]);
            float N = tanhf_(Dnx[e] + bxn1b[e & 1] + R * (Dnh[e] + bhn1b[e & 1]));
            hv[e] = N + Z * (h1own[e] - N);
            h1own[e] = hv[e];
        }
        CWAIT();               // S2(t): all h1s reads done -> overwrite safe
        {
            uint32_t a0h, a0l, a1h, a1l;
            split2(hv[0], hv[1], a0h, a0l);
            split2(hv[2], hv[3], a1h, a1l);
            uint32_t la = smem_u32(smq + QA_H1) + poff;
#pragma unroll
            for (int rk = 0; rk < CL_; ++rk)
                stc_v4(la, rk, a0h, a1h, a0l, a1l);
        }
        if (t == T_ - 1) {     // fp32 h1 -> owner rank's scratch
            float* scr = (float*)(smq + QSCR);
#pragma unroll
            for (int e = 0; e < 4; ++e) {
                int row = mt * 16 + gid + (e >> 1) * 8;
                int ug  = ug0 + (e & 1);
                uint32_t la = smem_u32(scr + (row & 7) * H_ + ug);
                stc_f32(la, row >> 3, hv[e]);
            }
        }
        CARRIVE();             // S3(t)
    }
    CWAIT();                   // final: scratch + h1 visible

    // ---- head ----
    const float* scr = (const float*)(smq + QSCR);
    float* hid = (float*)(smq + QA_X);
    if (tid < H_) {
        const float w2  = head_w2[tid];
        const float b1v = head_b1[tid];
        float acc[8];
#pragma unroll
        for (int r = 0; r < 8; ++r) acc[r] = b1v;
        for (int k4 = 0; k4 < 32; ++k4) {
            float4 wv = *(const float4*)(head_w1 + (size_t)tid * H_ + k4 * 4);
#pragma unroll
            for (int r = 0; r < 8; ++r) {
                float4 v = *(const float4*)(scr + r * H_ + k4 * 4);
                acc[r] += wv.x * v.x + wv.y * v.y + wv.z * v.z + wv.w * v.w;
            }
        }
#pragma unroll
        for (int r = 0; r < 8; ++r)
            hid[r * H_ + tid] = fmaxf(acc[r], 0.f) * w2;
    }
    __syncthreads();
    if (tid < 8) {
        float acc = head_b2[0];
        for (int k = 0; k < H_; ++k) acc += hid[tid * H_ + k];
        y[b0 + crank * 8 + tid] = acc;
    }
}

extern "C" void kernel_launch(void* const* d_in, const int* in_sizes, int n_in,
                              void* d_out, int out_size) {
    const float* x       = (const float*)d_in[0];
    const int*   ticker  = (const int*)  d_in[1];
    const float* embed   = (const float*)d_in[2];
    const float* W_ih0   = (const float*)d_in[3];
    const float* W_hh0   = (const float*)d_in[4];
    const float* b_ih0   = (const float*)d_in[5];
    const float* b_hh0   = (const float*)d_in[6];
    const float* W_ih1   = (const float*)d_in[7];
    const float* W_hh1   = (const float*)d_in[8];
    const float* b_ih1   = (const float*)d_in[9];
    const float* b_hh1   = (const float*)d_in[10];
    const float* head_w1 = (const float*)d_in[11];
    const float* head_b1 = (const float*)d_in[12];
    const float* head_w2 = (const float*)d_in[13];
    const float* head_b2 = (const float*)d_in[14];

    cudaFuncSetAttribute(gru_kernel,
                         cudaFuncAttributeMaxDynamicSharedMemorySize, SMEM_BYTES);

    cudaLaunchConfig_t cfg = {};
    cfg.gridDim  = dim3(NCTA, 1, 1);
    cfg.blockDim = dim3(NTHR, 1, 1);
    cfg.dynamicSmemBytes = SMEM_BYTES;
    cfg.stream = 0;
    cudaLaunchAttribute attr[1];
    attr[0].id = cudaLaunchAttributeClusterDimension;
    attr[0].val.clusterDim.x = CL_;
    attr[0].val.clusterDim.y = 1;
    attr[0].val.clusterDim.z = 1;
    cfg.attrs = attr;
    cfg.numAttrs = 1;

    cudaLaunchKernelEx(&cfg, gru_kernel,
                       x, ticker, embed,
                       b_ih0, b_hh0, b_ih1, b_hh1,
                       head_w1, head_b1, head_w2, head_b2,
                       W_ih0, W_hh0, W_ih1, W_hh1,
                       (float*)d_out);
}

// round 15
// speedup vs baseline: 10.1924x; 1.0887x over previous
#include <cuda_runtime.h>
#include <cuda_bf16.h>
#include <cstdint>

#define T_   512
#define F_   32
#define E_   16
#define H_   128
#define CL_  4
#define UN_  32
#define RWS_ 32
#define NCTA 128
#define NTHR 256

#define QB_HH0 0
#define QB_IH1 3072
#define QB_HH1 6144
#define QB_IH0 9216
#define QA_X   10368
#define QA_H0  10752
#define QA_H1  12800
#define QSCR   13824
#define SMEM_BYTES ((13824 + 256) * 16)

__device__ __forceinline__ float sigmoidf_(float v) {
    return 1.f / (1.f + __expf(-v));
}
__device__ __forceinline__ float tanhf_(float v) {
    v = fminf(fmaxf(v, -15.f), 15.f);
    float e = __expf(2.f * v);
    return (e - 1.f) / (e + 1.f);
}
__device__ __forceinline__ uint32_t smem_u32(const void* p) {
    uint32_t a;
    asm("{ .reg .u64 t; cvta.to.shared.u64 t, %1; cvt.u32.u64 %0, t; }"
        : "=r"(a) : "l"(p));
    return a;
}
__device__ __forceinline__ void stc_v4(uint32_t la, int rk, uint32_t a,
                                       uint32_t b, uint32_t c, uint32_t d) {
    asm volatile(
        "{ .reg .b32 ra;\n\t"
        "mapa.shared::cluster.u32 ra, %0, %1;\n\t"
        "st.shared::cluster.v4.b32 [ra], {%2, %3, %4, %5}; }"
        :: "r"(la), "r"(rk), "r"(a), "r"(b), "r"(c), "r"(d) : "memory");
}
__device__ __forceinline__ void stc_f32(uint32_t la, int rk, float v) {
    asm volatile(
        "{ .reg .b32 ra;\n\t"
        "mapa.shared::cluster.u32 ra, %0, %1;\n\t"
        "st.shared::cluster.f32 [ra], %2; }"
        :: "r"(la), "r"(rk), "f"(v) : "memory");
}
#define CARRIVE() asm volatile("barrier.cluster.arrive.aligned;" ::: "memory")
#define CWAIT()   asm volatile("barrier.cluster.wait.aligned;"   ::: "memory")

__device__ __forceinline__ void mma4(float* d, uint32_t a0, uint32_t a1,
                                     uint32_t a2, uint32_t a3,
                                     uint32_t b0, uint32_t b1) {
    asm("mma.sync.aligned.m16n8k16.row.col.f32.bf16.bf16.f32 "
        "{%0,%1,%2,%3},{%4,%5,%6,%7},{%8,%9},{%0,%1,%2,%3};"
        : "+f"(d[0]), "+f"(d[1]), "+f"(d[2]), "+f"(d[3])
        : "r"(a0), "r"(a1), "r"(a2), "r"(a3), "r"(b0), "r"(b1));
}

// 9 MMAs per ktile, gate-rotated so same-D RAW spacing is 3
#define MMA_KT_BODY(s0, s1, b0, b1, b2, Dr, Dz, Dn)            \
    mma4(Dr, (s0).x, (s0).y, (s1).x, (s1).y, (b0).x, (b0).y);  \
    mma4(Dz, (s0).x, (s0).y, (s1).x, (s1).y, (b1).x, (b1).y);  \
    mma4(Dn, (s0).x, (s0).y, (s1).x, (s1).y, (b2).x, (b2).y);  \
    mma4(Dr, (s0).z, (s0).w, (s1).z, (s1).w, (b0).x, (b0).y);  \
    mma4(Dz, (s0).z, (s0).w, (s1).z, (s1).w, (b1).x, (b1).y);  \
    mma4(Dn, (s0).z, (s0).w, (s1).z, (s1).w, (b2).x, (b2).y);  \
    mma4(Dr, (s0).x, (s0).y, (s1).x, (s1).y, (b0).z, (b0).w);  \
    mma4(Dz, (s0).x, (s0).y, (s1).x, (s1).y, (b1).z, (b1).w);  \
    mma4(Dn, (s0).x, (s0).y, (s1).x, (s1).y, (b2).z, (b2).w);

template<int KT>
__device__ __forceinline__ void mma_mat(const uint4* B, const uint4* A, int lane,
                                        float* Dr, float* Dz, float* Dn) {
#pragma unroll
    for (int kt = 0; kt < KT; ++kt) {
        uint4 s0 = A[(kt * 2 + 0) * 32 + lane];
        uint4 s1 = A[(kt * 2 + 1) * 32 + lane];
        uint4 b0 = B[(kt * 3 + 0) * 32 + lane];
        uint4 b1 = B[(kt * 3 + 1) * 32 + lane];
        uint4 b2 = B[(kt * 3 + 2) * 32 + lane];
        MMA_KT_BODY(s0, s1, b0, b1, b2, Dr, Dz, Dn)
    }
}
template<int KT>
__device__ __forceinline__ void mma_mat_areg(const uint4* B, const uint4* ar,
                                             int lane,
                                             float* Dr, float* Dz, float* Dn) {
#pragma unroll
    for (int kt = 0; kt < KT; ++kt) {
        uint4 b0 = B[(kt * 3 + 0) * 32 + lane];
        uint4 b1 = B[(kt * 3 + 1) * 32 + lane];
        uint4 b2 = B[(kt * 3 + 2) * 32 + lane];
        MMA_KT_BODY(ar[kt * 2], ar[kt * 2 + 1], b0, b1, b2, Dr, Dz, Dn)
    }
}

__device__ __forceinline__ void split2(float f0, float f1,
                                       uint32_t& hi, uint32_t& lo) {
    __nv_bfloat162 h = __floats2bfloat162_rn(f0, f1);
    float r0 = f0 - __bfloat162float(h.x);
    float r1 = f1 - __bfloat162float(h.y);
    __nv_bfloat162 l = __floats2bfloat162_rn(r0, r1);
    hi = *reinterpret_cast<uint32_t*>(&h);
    lo = *reinterpret_cast<uint32_t*>(&l);
}
__device__ __forceinline__ void wsplit(uint4* slotp, int boff, float w) {
    __nv_bfloat16 h = __float2bfloat16(w);
    __nv_bfloat16 l = __float2bfloat16(w - __bfloat162float(h));
    char* p = (char*)slotp;
    *(__nv_bfloat16*)(p + boff)     = h;
    *(__nv_bfloat16*)(p + 8 + boff) = l;
}

__global__ void __launch_bounds__(NTHR, 1) gru_kernel(
    const float* __restrict__ x,
    const int*   __restrict__ ticker,
    const float* __restrict__ embed,
    const float* __restrict__ b_ih0, const float* __restrict__ b_hh0,
    const float* __restrict__ b_ih1, const float* __restrict__ b_hh1,
    const float* __restrict__ head_w1, const float* __restrict__ head_b1,
    const float* __restrict__ head_w2, const float* __restrict__ head_b2,
    const float* __restrict__ W_ih0, const float* __restrict__ W_hh0,
    const float* __restrict__ W_ih1, const float* __restrict__ W_hh1,
    float* __restrict__ y)
{
    extern __shared__ __align__(16) uint4 smq[];
    const int tid   = threadIdx.x;
    const int lane  = tid & 31;
    const int w     = tid >> 5;
    const int mt    = w >> 2;
    const int q     = w & 3;
    const int gid   = lane >> 2;
    const int tig   = lane & 3;
    const int crank = blockIdx.x & 3;
    const int b0    = (blockIdx.x >> 2) * RWS_;

    for (int idx = tid; idx < 96 * H_; idx += NTHR) {
        int g = idx >> 7, k = idx & 127;
        int gt = g >> 5, ul = g & 31;
        int qq = ul >> 3, gidn = ul & 7;
        int kt = k >> 4, klo = k & 15;
        int boff = ((klo >> 3) & 1) * 4 + (klo & 1) * 2;
        int slot = ((qq * 8 + kt) * 3 + gt) * 32 + gidn * 4 + ((klo >> 1) & 3);
        size_t grow = (size_t)(gt * H_ + crank * UN_ + ul);
        wsplit(smq + QB_HH0 + slot, boff, W_hh0[grow * H_ + k]);
        wsplit(smq + QB_IH1 + slot, boff, W_ih1[grow * H_ + k]);
        wsplit(smq + QB_HH1 + slot, boff, W_hh1[grow * H_ + k]);
    }
    for (int idx = tid; idx < 96 * 48; idx += NTHR) {
        int g = idx / 48, k = idx % 48;
        int gt = g >> 5, ul = g & 31;
        int qq = ul >> 3, gidn = ul & 7;
        int kt = k >> 4, klo = k & 15;
        int boff = ((klo >> 3) & 1) * 4 + (klo & 1) * 2;
        int slot = ((qq * 3 + kt) * 3 + gt) * 32 + gidn * 4 + ((klo >> 1) & 3);
        size_t grow = (size_t)(gt * H_ + crank * UN_ + ul);
        wsplit(smq + QB_IH0 + slot, boff, W_ih0[grow * 48 + k]);
    }
    for (int i = tid; i < 12288; i += NTHR)
        ((uint32_t*)(smq + QA_H0))[i] = 0;

    {   // embed into x-plane kt=2 (constant)
        int r = tid >> 3, kp = 16 + (tid & 7);
        int e0 = 2 * kp - 32;
        float f0 = embed[(size_t)ticker[b0 + r] * E_ + e0];
        float f1 = embed[(size_t)ticker[b0 + r] * E_ + e0 + 1];
        int mtt = r >> 4, rl = r & 15;
        int ln = (rl & 7) * 4 + (kp & 3), h2 = (kp >> 2) & 1, kt = kp >> 3;
        uint4* sp = smq + QA_X + ((mtt * 3 + kt) * 2 + h2) * 32 + ln;
        uint32_t hi, lo; split2(f0, f1, hi, lo);
        ((uint32_t*)sp)[rl >> 3] = hi;
        ((uint32_t*)sp)[2 + (rl >> 3)] = lo;
    }
#pragma unroll
    for (int s = 0; s < 2; ++s) {   // x(t=0)
        int p2 = tid * 2 + s;
        int r = p2 >> 4, kp = p2 & 15;
        float2 v = *(const float2*)(x + ((size_t)(b0 + r) * T_) * F_ + 2 * kp);
        int mtt = r >> 4, rl = r & 15;
        int ln = (rl & 7) * 4 + (kp & 3), h2 = (kp >> 2) & 1, kt = kp >> 3;
        uint4* sp = smq + QA_X + ((mtt * 3 + kt) * 2 + h2) * 32 + ln;
        uint32_t hi, lo; split2(v.x, v.y, hi, lo);
        ((uint32_t*)sp)[rl >> 3] = hi;
        ((uint32_t*)sp)[2 + (rl >> 3)] = lo;
    }
    const int ug0 = crank * 32 + q * 8 + 2 * tig;
    float br0b[2], bz0b[2], bxn0b[2], bhn0b[2];
    float br1b[2], bz1b[2], bxn1b[2], bhn1b[2];
#pragma unroll
    for (int e = 0; e < 2; ++e) {
        int j = ug0 + e;
        br0b[e]  = b_ih0[j] + b_hh0[j];
        bz0b[e]  = b_ih0[H_ + j] + b_hh0[H_ + j];
        bxn0b[e] = b_ih0[2 * H_ + j];
        bhn0b[e] = b_hh0[2 * H_ + j];
        br1b[e]  = b_ih1[j] + b_hh1[j];
        bz1b[e]  = b_ih1[H_ + j] + b_hh1[H_ + j];
        bxn1b[e] = b_ih1[2 * H_ + j];
        bhn1b[e] = b_hh1[2 * H_ + j];
    }
    float h0own[4] = {0.f, 0.f, 0.f, 0.f};
    float h1own[4] = {0.f, 0.f, 0.f, 0.f};

    const int pkt = crank * 2 + (q >> 1);
    const int ph2 = q & 1;
    const uint32_t poff = (uint32_t)(((mt * 8 + pkt) * 2 + ph2) * 32 + lane) * 16u;

    __syncthreads();
    CARRIVE(); CWAIT();        // all init visible cluster-wide
    CARRIVE();                 // prime: pairs with first W(S3')

#pragma unroll 1
    for (int t = 0; t < T_; ++t) {
        const uint4* AH0c = smq + QA_H0 + (t & 1) * 1024 + mt * 512;
        const uint4* AH0n = smq + QA_H0 + ((t + 1) & 1) * 1024 + mt * 512;
        uint4* AH0n_pl    = smq + QA_H0 + ((t + 1) & 1) * 1024;
        float Dr0[4] = {0,0,0,0}, Dz0[4] = {0,0,0,0}, Dnx[4] = {0,0,0,0};
        float Dr1[4] = {0,0,0,0}, Dz1[4] = {0,0,0,0}, Dnh[4] = {0,0,0,0};
        float hv[4];

        // ---- layer 0 ----
        mma_mat<3>(smq + QB_IH0 + q * 288, smq + QA_X + mt * 192, lane,
                   Dr0, Dz0, Dnx);
        mma_mat<8>(smq + QB_HH0 + q * 768, AH0c, lane, Dr1, Dz1, Dnh);
#pragma unroll
        for (int e = 0; e < 4; ++e) {
            float R = sigmoidf_(Dr0[e] + Dr1[e] + br0b[e & 1]);
            float Z = sigmoidf_(Dz0[e] + Dz1[e] + bz0b[e & 1]);
            float N = tanhf_(Dnx[e] + bxn0b[e & 1] + R * (Dnh[e] + bhn0b[e & 1]));
            hv[e] = N + Z * (h0own[e] - N);
            h0own[e] = hv[e];
        }
        {   // publish h0(t)
            uint32_t a0h, a0l, a1h, a1l;
            split2(hv[0], hv[1], a0h, a0l);
            split2(hv[2], hv[3], a1h, a1l);
            uint32_t la = smem_u32(AH0n_pl) + poff;
#pragma unroll
            for (int rk = 0; rk < CL_; ++rk)
                stc_v4(la, rk, a0h, a1h, a0l, a1l);
        }
        CWAIT();               // S3(t-1): h1(t-1) publishes visible

        // preload h1(t-1) A-fragments into registers BEFORE arriving S1:
        // W(S1) then also certifies "all h1 reads done" -> S2 eliminated
        uint4 hf[16];
        {
            const uint4* H1p = smq + QA_H1 + mt * 512;
#pragma unroll
            for (int i = 0; i < 16; ++i) hf[i] = H1p[i * 32 + lane];
        }
        CARRIVE();             // S1(t): h0 publish issued + h1 reads done

        // layer 1 hh-part from registers (hides S1 drain). RESET accums first.
#pragma unroll
        for (int e = 0; e < 4; ++e) { Dr1[e] = 0.f; Dz1[e] = 0.f; Dnh[e] = 0.f; }
        mma_mat_areg<8>(smq + QB_HH1 + q * 768, hf, lane, Dr1, Dz1, Dnh);
        CWAIT();               // S1(t): h0(t) visible; h1 buffer free

        if (t + 1 < T_) {      // restage x(t+1)
#pragma unroll
            for (int s = 0; s < 2; ++s) {
                int p2 = tid * 2 + s;
                int r = p2 >> 4, kp = p2 & 15;
                float2 v = *(const float2*)
                    (x + ((size_t)(b0 + r) * T_ + t + 1) * F_ + 2 * kp);
                int mtt = r >> 4, rl = r & 15;
                int ln = (rl & 7) * 4 + (kp & 3), h2 = (kp >> 2) & 1, kt = kp >> 3;
                uint4* sp = smq + QA_X + ((mtt * 3 + kt) * 2 + h2) * 32 + ln;
                uint32_t hi, lo; split2(v.x, v.y, hi, lo);
                ((uint32_t*)sp)[rl >> 3] = hi;
                ((uint32_t*)sp)[2 + (rl >> 3)] = lo;
            }
        }

        // layer 1 ih-part (reads h0(t)). RESET accums first.
#pragma unroll
        for (int e = 0; e < 4; ++e) { Dr0[e] = 0.f; Dz0[e] = 0.f; Dnx[e] = 0.f; }
        mma_mat<8>(smq + QB_IH1 + q * 768, AH0n, lane, Dr0, Dz0, Dnx);
#pragma unroll
        for (int e = 0; e < 4; ++e) {
            float R = sigmoidf_(Dr0[e] + Dr1[e] + br1b[e & 1]);
            float Z = sigmoidf_(Dz0[e] + Dz1[e] + bz1b[e & 1]);
            float N = tanhf_(Dnx[e] + bxn1b[e & 1] + R * (Dnh[e] + bhn1b[e & 1]));
            hv[e] = N + Z * (h1own[e] - N);
            h1own[e] = hv[e];
        }
        {   // publish h1(t) into the (now free) single buffer
            uint32_t a0h, a0l, a1h, a1l;
            split2(hv[0], hv[1], a0h, a0l);
            split2(hv[2], hv[3], a1h, a1l);
            uint32_t la = smem_u32(smq + QA_H1) + poff;
#pragma unroll
            for (int rk = 0; rk < CL_; ++rk)
                stc_v4(la, rk, a0h, a1h, a0l, a1l);
        }
        if (t == T_ - 1) {
            float* scr = (float*)(smq + QSCR);
#pragma unroll
            for (int e = 0; e < 4; ++e) {
                int row = mt * 16 + gid + (e >> 1) * 8;
                int ug  = ug0 + (e & 1);
                uint32_t la = smem_u32(scr + (row & 7) * H_ + ug);
                stc_f32(la, row >> 3, hv[e]);
            }
        }
        CARRIVE();             // S3(t)
        __syncthreads();       // orders x restage vs next iteration's reads
    }
    CWAIT();                   // final S3: h1 + scratch visible

    // ---- head ----
    const float* scr = (const float*)(smq + QSCR);
    float* hid = (float*)(smq + QA_X);
    if (tid < H_) {
        const float w2  = head_w2[tid];
        const float b1v = head_b1[tid];
        float acc[8];
#pragma unroll
        for (int r = 0; r < 8; ++r) acc[r] = b1v;
        for (int k4 = 0; k4 < 32; ++k4) {
            float4 wv = *(const float4*)(head_w1 + (size_t)tid * H_ + k4 * 4);
#pragma unroll
            for (int r = 0; r < 8; ++r) {
                float4 v = *(const float4*)(scr + r * H_ + k4 * 4);
                acc[r] += wv.x * v.x + wv.y * v.y + wv.z * v.z + wv.w * v.w;
            }
        }
#pragma unroll
        for (int r = 0; r < 8; ++r)
            hid[r * H_ + tid] = fmaxf(acc[r], 0.f) * w2;
    }
    __syncthreads();
    if (tid < 8) {
        float acc = head_b2[0];
        for (int k = 0; k < H_; ++k) acc += hid[tid * H_ + k];
        y[b0 + crank * 8 + tid] = acc;
    }
}

extern "C" void kernel_launch(void* const* d_in, const int* in_sizes, int n_in,
                              void* d_out, int out_size) {
    const float* x       = (const float*)d_in[0];
    const int*   ticker  = (const int*)  d_in[1];
    const float* embed   = (const float*)d_in[2];
    const float* W_ih0   = (const float*)d_in[3];
    const float* W_hh0   = (const float*)d_in[4];
    const float* b_ih0   = (const float*)d_in[5];
    const float* b_hh0   = (const float*)d_in[6];
    const float* W_ih1   = (const float*)d_in[7];
    const float* W_hh1   = (const float*)d_in[8];
    const float* b_ih1   = (const float*)d_in[9];
    const float* b_hh1   = (const float*)d_in[10];
    const float* head_w1 = (const float*)d_in[11];
    const float* head_b1 = (const float*)d_in[12];
    const float* head_w2 = (const float*)d_in[13];
    const float* head_b2 = (const float*)d_in[14];

    cudaFuncSetAttribute(gru_kernel,
                         cudaFuncAttributeMaxDynamicSharedMemorySize, SMEM_BYTES);

    cudaLaunchConfig_t cfg = {};
    cfg.gridDim  = dim3(NCTA, 1, 1);
    cfg.blockDim = dim3(NTHR, 1, 1);
    cfg.dynamicSmemBytes = SMEM_BYTES;
    cfg.stream = 0;
    cudaLaunchAttribute attr[1];
    attr[0].id = cudaLaunchAttributeClusterDimension;
    attr[0].val.clusterDim.x = CL_;
    attr[0].val.clusterDim.y = 1;
    attr[0].val.clusterDim.z = 1;
    cfg.attrs = attr;
    cfg.numAttrs = 1;

    cudaLaunchKernelEx(&cfg, gru_kernel,
                       x, ticker, embed,
                       b_ih0, b_hh0, b_ih1, b_hh1,
                       head_w1, head_b1, head_w2, head_b2,
                       W_ih0, W_hh0, W_ih1, W_hh1,
                       (float*)d_out);
}

// round 16
// speedup vs baseline: 11.6925x; 1.1472x over previous
#include <cuda_runtime.h>
#include <cuda_bf16.h>
#include <cstdint>

#define T_   512
#define F_   32
#define E_   16
#define H_   128
#define CL_  4
#define UN_  32
#define RWS_ 32
#define NCTA 128
#define NTHR 512   // 16 warps: gw = w>>3 (0=L0,1=L1), wl = w&7 -> mt,q

#define QB_HH0 0
#define QB_IH1 3072
#define QB_HH1 6144
#define QB_IH0 9216
#define QA_X   10368
#define QA_H0  10752
#define QA_H1  12800
#define QSCR   13824
#define SMEM_BYTES ((13824 + 256) * 16)

__device__ __forceinline__ float sigmoidf_(float v) {
    return 1.f / (1.f + __expf(-v));
}
__device__ __forceinline__ float tanhf_(float v) {
    v = fminf(fmaxf(v, -15.f), 15.f);
    float e = __expf(2.f * v);
    return (e - 1.f) / (e + 1.f);
}
__device__ __forceinline__ uint32_t smem_u32(const void* p) {
    uint32_t a;
    asm("{ .reg .u64 t; cvta.to.shared.u64 t, %1; cvt.u32.u64 %0, t; }"
        : "=r"(a) : "l"(p));
    return a;
}
__device__ __forceinline__ void stc_v4(uint32_t la, int rk, uint32_t a,
                                       uint32_t b, uint32_t c, uint32_t d) {
    asm volatile(
        "{ .reg .b32 ra;\n\t"
        "mapa.shared::cluster.u32 ra, %0, %1;\n\t"
        "st.shared::cluster.v4.b32 [ra], {%2, %3, %4, %5}; }"
        :: "r"(la), "r"(rk), "r"(a), "r"(b), "r"(c), "r"(d) : "memory");
}
__device__ __forceinline__ void stc_f32(uint32_t la, int rk, float v) {
    asm volatile(
        "{ .reg .b32 ra;\n\t"
        "mapa.shared::cluster.u32 ra, %0, %1;\n\t"
        "st.shared::cluster.f32 [ra], %2; }"
        :: "r"(la), "r"(rk), "f"(v) : "memory");
}
#define CARRIVE() asm volatile("barrier.cluster.arrive.aligned;" ::: "memory")
#define CWAIT()   asm volatile("barrier.cluster.wait.aligned;"   ::: "memory")

__device__ __forceinline__ void mma4(float* d, uint32_t a0, uint32_t a1,
                                     uint32_t a2, uint32_t a3,
                                     uint32_t b0, uint32_t b1) {
    asm("mma.sync.aligned.m16n8k16.row.col.f32.bf16.bf16.f32 "
        "{%0,%1,%2,%3},{%4,%5,%6,%7},{%8,%9},{%0,%1,%2,%3};"
        : "+f"(d[0]), "+f"(d[1]), "+f"(d[2]), "+f"(d[3])
        : "r"(a0), "r"(a1), "r"(a2), "r"(a3), "r"(b0), "r"(b1));
}

#define MMA_KT_BODY(s0, s1, b0, b1, b2, Dr, Dz, Dn)            \
    mma4(Dr, (s0).x, (s0).y, (s1).x, (s1).y, (b0).x, (b0).y);  \
    mma4(Dz, (s0).x, (s0).y, (s1).x, (s1).y, (b1).x, (b1).y);  \
    mma4(Dn, (s0).x, (s0).y, (s1).x, (s1).y, (b2).x, (b2).y);  \
    mma4(Dr, (s0).z, (s0).w, (s1).z, (s1).w, (b0).x, (b0).y);  \
    mma4(Dz, (s0).z, (s0).w, (s1).z, (s1).w, (b1).x, (b1).y);  \
    mma4(Dn, (s0).z, (s0).w, (s1).z, (s1).w, (b2).x, (b2).y);  \
    mma4(Dr, (s0).x, (s0).y, (s1).x, (s1).y, (b0).z, (b0).w);  \
    mma4(Dz, (s0).x, (s0).y, (s1).x, (s1).y, (b1).z, (b1).w);  \
    mma4(Dn, (s0).x, (s0).y, (s1).x, (s1).y, (b2).z, (b2).w);

template<int KT>
__device__ __forceinline__ void mma_mat(const uint4* B, const uint4* A, int lane,
                                        float* Dr, float* Dz, float* Dn) {
#pragma unroll
    for (int kt = 0; kt < KT; ++kt) {
        uint4 s0 = A[(kt * 2 + 0) * 32 + lane];
        uint4 s1 = A[(kt * 2 + 1) * 32 + lane];
        uint4 b0 = B[(kt * 3 + 0) * 32 + lane];
        uint4 b1 = B[(kt * 3 + 1) * 32 + lane];
        uint4 b2 = B[(kt * 3 + 2) * 32 + lane];
        MMA_KT_BODY(s0, s1, b0, b1, b2, Dr, Dz, Dn)
    }
}

__device__ __forceinline__ void split2(float f0, float f1,
                                       uint32_t& hi, uint32_t& lo) {
    __nv_bfloat162 h = __floats2bfloat162_rn(f0, f1);
    float r0 = f0 - __bfloat162float(h.x);
    float r1 = f1 - __bfloat162float(h.y);
    __nv_bfloat162 l = __floats2bfloat162_rn(r0, r1);
    hi = *reinterpret_cast<uint32_t*>(&h);
    lo = *reinterpret_cast<uint32_t*>(&l);
}
__device__ __forceinline__ void wsplit(uint4* slotp, int boff, float w) {
    __nv_bfloat16 h = __float2bfloat16(w);
    __nv_bfloat16 l = __float2bfloat16(w - __bfloat162float(h));
    char* p = (char*)slotp;
    *(__nv_bfloat16*)(p + boff)     = h;
    *(__nv_bfloat16*)(p + 8 + boff) = l;
}

__global__ void __launch_bounds__(NTHR, 1) gru_kernel(
    const float* __restrict__ x,
    const int*   __restrict__ ticker,
    const float* __restrict__ embed,
    const float* __restrict__ b_ih0, const float* __restrict__ b_hh0,
    const float* __restrict__ b_ih1, const float* __restrict__ b_hh1,
    const float* __restrict__ head_w1, const float* __restrict__ head_b1,
    const float* __restrict__ head_w2, const float* __restrict__ head_b2,
    const float* __restrict__ W_ih0, const float* __restrict__ W_hh0,
    const float* __restrict__ W_ih1, const float* __restrict__ W_hh1,
    float* __restrict__ y)
{
    extern __shared__ __align__(16) uint4 smq[];
    const int tid   = threadIdx.x;
    const int lane  = tid & 31;
    const int w     = tid >> 5;
    const int gw    = w >> 3;            // 0 = layer-0 group, 1 = layer-1 group
    const int wl    = w & 7;
    const int mt    = wl >> 2;
    const int q     = wl & 3;
    const int gid   = lane >> 2;
    const int tig   = lane & 3;
    const int crank = blockIdx.x & 3;
    const int b0    = (blockIdx.x >> 2) * RWS_;

    for (int idx = tid; idx < 96 * H_; idx += NTHR) {
        int g = idx >> 7, k = idx & 127;
        int gt = g >> 5, ul = g & 31;
        int qq = ul >> 3, gidn = ul & 7;
        int kt = k >> 4, klo = k & 15;
        int boff = ((klo >> 3) & 1) * 4 + (klo & 1) * 2;
        int slot = ((qq * 8 + kt) * 3 + gt) * 32 + gidn * 4 + ((klo >> 1) & 3);
        size_t grow = (size_t)(gt * H_ + crank * UN_ + ul);
        wsplit(smq + QB_HH0 + slot, boff, W_hh0[grow * H_ + k]);
        wsplit(smq + QB_IH1 + slot, boff, W_ih1[grow * H_ + k]);
        wsplit(smq + QB_HH1 + slot, boff, W_hh1[grow * H_ + k]);
    }
    for (int idx = tid; idx < 96 * 48; idx += NTHR) {
        int g = idx / 48, k = idx % 48;
        int gt = g >> 5, ul = g & 31;
        int qq = ul >> 3, gidn = ul & 7;
        int kt = k >> 4, klo = k & 15;
        int boff = ((klo >> 3) & 1) * 4 + (klo & 1) * 2;
        int slot = ((qq * 3 + kt) * 3 + gt) * 32 + gidn * 4 + ((klo >> 1) & 3);
        size_t grow = (size_t)(gt * H_ + crank * UN_ + ul);
        wsplit(smq + QB_IH0 + slot, boff, W_ih0[grow * 48 + k]);
    }
    for (int i = tid; i < 12288; i += NTHR)
        ((uint32_t*)(smq + QA_H0))[i] = 0;

    if (tid < 256) {   // embed into x-plane kt=2 (constant)
        int r = tid >> 3, kp = 16 + (tid & 7);
        int e0 = 2 * kp - 32;
        float f0 = embed[(size_t)ticker[b0 + r] * E_ + e0];
        float f1 = embed[(size_t)ticker[b0 + r] * E_ + e0 + 1];
        int mtt = r >> 4, rl = r & 15;
        int ln = (rl & 7) * 4 + (kp & 3), h2 = (kp >> 2) & 1, kt = kp >> 3;
        uint4* sp = smq + QA_X + ((mtt * 3 + kt) * 2 + h2) * 32 + ln;
        uint32_t hi, lo; split2(f0, f1, hi, lo);
        ((uint32_t*)sp)[rl >> 3] = hi;
        ((uint32_t*)sp)[2 + (rl >> 3)] = lo;
    }
    {   // x(t=0): 512 float2 pieces, one per thread
        int r = tid >> 4, kp = tid & 15;
        float2 v = *(const float2*)(x + ((size_t)(b0 + r) * T_) * F_ + 2 * kp);
        int mtt = r >> 4, rl = r & 15;
        int ln = (rl & 7) * 4 + (kp & 3), h2 = (kp >> 2) & 1, kt = kp >> 3;
        uint4* sp = smq + QA_X + ((mtt * 3 + kt) * 2 + h2) * 32 + ln;
        uint32_t hi, lo; split2(v.x, v.y, hi, lo);
        ((uint32_t*)sp)[rl >> 3] = hi;
        ((uint32_t*)sp)[2 + (rl >> 3)] = lo;
    }
    // biases: group 0 loads layer-0, group 1 loads layer-1
    const int ug0 = crank * 32 + q * 8 + 2 * tig;
    float brb[2], bzb[2], bxnb[2], bhnb[2];
#pragma unroll
    for (int e = 0; e < 2; ++e) {
        int j = ug0 + e;
        if (gw == 0) {
            brb[e]  = b_ih0[j] + b_hh0[j];
            bzb[e]  = b_ih0[H_ + j] + b_hh0[H_ + j];
            bxnb[e] = b_ih0[2 * H_ + j];
            bhnb[e] = b_hh0[2 * H_ + j];
        } else {
            brb[e]  = b_ih1[j] + b_hh1[j];
            bzb[e]  = b_ih1[H_ + j] + b_hh1[H_ + j];
            bxnb[e] = b_ih1[2 * H_ + j];
            bhnb[e] = b_hh1[2 * H_ + j];
        }
    }
    float hown[4] = {0.f, 0.f, 0.f, 0.f};   // h0own (gw=0) or h1own (gw=1)

    const int pkt = crank * 2 + (q >> 1);
    const int ph2 = q & 1;
    const uint32_t poff = (uint32_t)(((mt * 8 + pkt) * 2 + ph2) * 32 + lane) * 16u;

    __syncthreads();
    CARRIVE(); CWAIT();        // all init visible cluster-wide

#pragma unroll 1
    for (int i = 0; i <= T_; ++i) {
        const uint4* H0cur = smq + QA_H0 + (i & 1) * 1024 + mt * 512;
        uint4* H0nxt_pl    = smq + QA_H0 + ((i + 1) & 1) * 1024;
        float hv[4];
        bool active = (gw == 0) ? (i < T_) : (i >= 1);

        if (active) {
            float Dr0[4] = {0,0,0,0}, Dz0[4] = {0,0,0,0}, Dnx[4] = {0,0,0,0};
            float Dr1[4] = {0,0,0,0}, Dz1[4] = {0,0,0,0}, Dnh[4] = {0,0,0,0};
            if (gw == 0) {
                // L0(i): ih = x(i), hh = h0(i-1)
                mma_mat<3>(smq + QB_IH0 + q * 288, smq + QA_X + mt * 192, lane,
                           Dr0, Dz0, Dnx);
                mma_mat<8>(smq + QB_HH0 + q * 768, H0cur, lane, Dr1, Dz1, Dnh);
            } else {
                // L1(i-1): hh = h1(i-2) from SMEM, ih = h0(i-1)
                mma_mat<8>(smq + QB_HH1 + q * 768, smq + QA_H1 + mt * 512, lane,
                           Dr1, Dz1, Dnh);
                mma_mat<8>(smq + QB_IH1 + q * 768, H0cur, lane, Dr0, Dz0, Dnx);
            }
#pragma unroll
            for (int e = 0; e < 4; ++e) {
                float R = sigmoidf_(Dr0[e] + Dr1[e] + brb[e & 1]);
                float Z = sigmoidf_(Dz0[e] + Dz1[e] + bzb[e & 1]);
                float N = tanhf_(Dnx[e] + bxnb[e & 1] + R * (Dnh[e] + bhnb[e & 1]));
                hv[e] = N + Z * (hown[e] - N);
                hown[e] = hv[e];
            }
            if (gw == 0) {   // publish h0(i) into the free buffer (pre-sync)
                uint32_t a0h, a0l, a1h, a1l;
                split2(hv[0], hv[1], a0h, a0l);
                split2(hv[2], hv[3], a1h, a1l);
                uint32_t la = smem_u32(H0nxt_pl) + poff;
#pragma unroll
                for (int rk = 0; rk < CL_; ++rk)
                    stc_v4(la, rk, a0h, a1h, a0l, a1l);
            }
        }
        CARRIVE(); CWAIT();    // SYNC1: h0(i) visible; all h1(i-2) reads done

        if (gw == 1 && i >= 1) {   // publish h1(i-1) (visible after SYNC of i+1)
            uint32_t a0h, a0l, a1h, a1l;
            split2(hv[0], hv[1], a0h, a0l);
            split2(hv[2], hv[3], a1h, a1l);
            uint32_t la = smem_u32(smq + QA_H1) + poff;
#pragma unroll
            for (int rk = 0; rk < CL_; ++rk)
                stc_v4(la, rk, a0h, a1h, a0l, a1l);
            if (i == T_) {   // final h1 -> fp32 scratch for head
                float* scr = (float*)(smq + QSCR);
#pragma unroll
                for (int e = 0; e < 4; ++e) {
                    int row = mt * 16 + gid + (e >> 1) * 8;
                    int ug  = ug0 + (e & 1);
                    uint32_t la2 = smem_u32(scr + (row & 7) * H_ + ug);
                    stc_f32(la2, row >> 3, hv[e]);
                }
            }
        }
        if (i + 1 < T_) {      // restage x(i+1): readers certified by SYNC1
            int r = tid >> 4, kp = tid & 15;
            float2 v = *(const float2*)
                (x + ((size_t)(b0 + r) * T_ + i + 1) * F_ + 2 * kp);
            int mtt = r >> 4, rl = r & 15;
            int ln = (rl & 7) * 4 + (kp & 3), h2 = (kp >> 2) & 1, kt = kp >> 3;
            uint4* sp = smq + QA_X + ((mtt * 3 + kt) * 2 + h2) * 32 + ln;
            uint32_t hi, lo; split2(v.x, v.y, hi, lo);
            ((uint32_t*)sp)[rl >> 3] = hi;
            ((uint32_t*)sp)[2 + (rl >> 3)] = lo;
        }
        CARRIVE(); CWAIT();    // SYNC2: h1(i-1) + x(i+1) visible for next iter
    }

    // ---- head ----
    const float* scr = (const float*)(smq + QSCR);
    float* hid = (float*)(smq + QA_X);
    if (tid < H_) {
        const float w2  = head_w2[tid];
        const float b1v = head_b1[tid];
        float acc[8];
#pragma unroll
        for (int r = 0; r < 8; ++r) acc[r] = b1v;
        for (int k4 = 0; k4 < 32; ++k4) {
            float4 wv = *(const float4*)(head_w1 + (size_t)tid * H_ + k4 * 4);
#pragma unroll
            for (int r = 0; r < 8; ++r) {
                float4 v = *(const float4*)(scr + r * H_ + k4 * 4);
                acc[r] += wv.x * v.x + wv.y * v.y + wv.z * v.z + wv.w * v.w;
            }
        }
#pragma unroll
        for (int r = 0; r < 8; ++r)
            hid[r * H_ + tid] = fmaxf(acc[r], 0.f) * w2;
    }
    __syncthreads();
    if (tid < 8) {
        float acc = head_b2[0];
        for (int k = 0; k < H_; ++k) acc += hid[tid * H_ + k];
        y[b0 + crank * 8 + tid] = acc;
    }
}

extern "C" void kernel_launch(void* const* d_in, const int* in_sizes, int n_in,
                              void* d_out, int out_size) {
    const float* x       = (const float*)d_in[0];
    const int*   ticker  = (const int*)  d_in[1];
    const float* embed   = (const float*)d_in[2];
    const float* W_ih0   = (const float*)d_in[3];
    const float* W_hh0   = (const float*)d_in[4];
    const float* b_ih0   = (const float*)d_in[5];
    const float* b_hh0   = (const float*)d_in[6];
    const float* W_ih1   = (const float*)d_in[7];
    const float* W_hh1   = (const float*)d_in[8];
    const float* b_ih1   = (const float*)d_in[9];
    const float* b_hh1   = (const float*)d_in[10];
    const float* head_w1 = (const float*)d_in[11];
    const float* head_b1 = (const float*)d_in[12];
    const float* head_w2 = (const float*)d_in[13];
    const float* head_b2 = (const float*)d_in[14];

    cudaFuncSetAttribute(gru_kernel,
                         cudaFuncAttributeMaxDynamicSharedMemorySize, SMEM_BYTES);

    cudaLaunchConfig_t cfg = {};
    cfg.gridDim  = dim3(NCTA, 1, 1);
    cfg.blockDim = dim3(NTHR, 1, 1);
    cfg.dynamicSmemBytes = SMEM_BYTES;
    cfg.stream = 0;
    cudaLaunchAttribute attr[1];
    attr[0].id = cudaLaunchAttributeClusterDimension;
    attr[0].val.clusterDim.x = CL_;
    attr[0].val.clusterDim.y = 1;
    attr[0].val.clusterDim.z = 1;
    cfg.attrs = attr;
    cfg.numAttrs = 1;

    cudaLaunchKernelEx(&cfg, gru_kernel,
                       x, ticker, embed,
                       b_ih0, b_hh0, b_ih1, b_hh1,
                       head_w1, head_b1, head_w2, head_b2,
                       W_ih0, W_hh0, W_ih1, W_hh1,
                       (float*)d_out);
}

// round 17
// speedup vs baseline: 12.3376x; 1.0552x over previous
#include <cuda_runtime.h>
#include <cuda_bf16.h>
#include <cstdint>

#define T_   512
#define F_   32
#define E_   16
#define H_   128
#define CL_  4
#define UN_  32
#define RWS_ 32
#define NCTA 128
#define NTHR 512   // 16 warps: gw = w>>3 (0=L0,1=L1), wl = w&7 -> mt,q

#define QB_HH0 0
#define QB_IH1 3072
#define QB_HH1 6144
#define QB_IH0 9216
#define QA_X   10368
#define QA_H0  10752
#define QA_H1  12800
#define QSCR   13824
#define SMEM_BYTES ((13824 + 256) * 16)

__device__ __forceinline__ float sigmoidf_(float v) {
    return 1.f / (1.f + __expf(-v));
}
__device__ __forceinline__ float tanhf_(float v) {
    v = fminf(fmaxf(v, -15.f), 15.f);
    float e = __expf(2.f * v);
    return (e - 1.f) / (e + 1.f);
}
__device__ __forceinline__ uint32_t smem_u32(const void* p) {
    uint32_t a;
    asm("{ .reg .u64 t; cvta.to.shared.u64 t, %1; cvt.u32.u64 %0, t; }"
        : "=r"(a) : "l"(p));
    return a;
}
__device__ __forceinline__ void stc_v4(uint32_t la, int rk, uint32_t a,
                                       uint32_t b, uint32_t c, uint32_t d) {
    asm volatile(
        "{ .reg .b32 ra;\n\t"
        "mapa.shared::cluster.u32 ra, %0, %1;\n\t"
        "st.shared::cluster.v4.b32 [ra], {%2, %3, %4, %5}; }"
        :: "r"(la), "r"(rk), "r"(a), "r"(b), "r"(c), "r"(d) : "memory");
}
__device__ __forceinline__ void stc_f32(uint32_t la, int rk, float v) {
    asm volatile(
        "{ .reg .b32 ra;\n\t"
        "mapa.shared::cluster.u32 ra, %0, %1;\n\t"
        "st.shared::cluster.f32 [ra], %2; }"
        :: "r"(la), "r"(rk), "f"(v) : "memory");
}
#define CARRIVE() asm volatile("barrier.cluster.arrive.aligned;" ::: "memory")
#define CWAIT()   asm volatile("barrier.cluster.wait.aligned;"   ::: "memory")

__device__ __forceinline__ void mma4(float* d, uint32_t a0, uint32_t a1,
                                     uint32_t a2, uint32_t a3,
                                     uint32_t b0, uint32_t b1) {
    asm("mma.sync.aligned.m16n8k16.row.col.f32.bf16.bf16.f32 "
        "{%0,%1,%2,%3},{%4,%5,%6,%7},{%8,%9},{%0,%1,%2,%3};"
        : "+f"(d[0]), "+f"(d[1]), "+f"(d[2]), "+f"(d[3])
        : "r"(a0), "r"(a1), "r"(a2), "r"(a3), "r"(b0), "r"(b1));
}

#define MMA_KT_BODY(s0, s1, b0, b1, b2, Dr, Dz, Dn)            \
    mma4(Dr, (s0).x, (s0).y, (s1).x, (s1).y, (b0).x, (b0).y);  \
    mma4(Dz, (s0).x, (s0).y, (s1).x, (s1).y, (b1).x, (b1).y);  \
    mma4(Dn, (s0).x, (s0).y, (s1).x, (s1).y, (b2).x, (b2).y);  \
    mma4(Dr, (s0).z, (s0).w, (s1).z, (s1).w, (b0).x, (b0).y);  \
    mma4(Dz, (s0).z, (s0).w, (s1).z, (s1).w, (b1).x, (b1).y);  \
    mma4(Dn, (s0).z, (s0).w, (s1).z, (s1).w, (b2).x, (b2).y);  \
    mma4(Dr, (s0).x, (s0).y, (s1).x, (s1).y, (b0).z, (b0).w);  \
    mma4(Dz, (s0).x, (s0).y, (s1).x, (s1).y, (b1).z, (b1).w);  \
    mma4(Dn, (s0).x, (s0).y, (s1).x, (s1).y, (b2).z, (b2).w);

template<int KT>
__device__ __forceinline__ void mma_mat(const uint4* B, const uint4* A, int lane,
                                        float* Dr, float* Dz, float* Dn) {
#pragma unroll
    for (int kt = 0; kt < KT; ++kt) {
        uint4 s0 = A[(kt * 2 + 0) * 32 + lane];
        uint4 s1 = A[(kt * 2 + 1) * 32 + lane];
        uint4 b0 = B[(kt * 3 + 0) * 32 + lane];
        uint4 b1 = B[(kt * 3 + 1) * 32 + lane];
        uint4 b2 = B[(kt * 3 + 2) * 32 + lane];
        MMA_KT_BODY(s0, s1, b0, b1, b2, Dr, Dz, Dn)
    }
}

__device__ __forceinline__ void split2(float f0, float f1,
                                       uint32_t& hi, uint32_t& lo) {
    __nv_bfloat162 h = __floats2bfloat162_rn(f0, f1);
    float r0 = f0 - __bfloat162float(h.x);
    float r1 = f1 - __bfloat162float(h.y);
    __nv_bfloat162 l = __floats2bfloat162_rn(r0, r1);
    hi = *reinterpret_cast<uint32_t*>(&h);
    lo = *reinterpret_cast<uint32_t*>(&l);
}
__device__ __forceinline__ void wsplit(uint4* slotp, int boff, float w) {
    __nv_bfloat16 h = __float2bfloat16(w);
    __nv_bfloat16 l = __float2bfloat16(w - __bfloat162float(h));
    char* p = (char*)slotp;
    *(__nv_bfloat16*)(p + boff)     = h;
    *(__nv_bfloat16*)(p + 8 + boff) = l;
}

__global__ void __launch_bounds__(NTHR, 1) gru_kernel(
    const float* __restrict__ x,
    const int*   __restrict__ ticker,
    const float* __restrict__ embed,
    const float* __restrict__ b_ih0, const float* __restrict__ b_hh0,
    const float* __restrict__ b_ih1, const float* __restrict__ b_hh1,
    const float* __restrict__ head_w1, const float* __restrict__ head_b1,
    const float* __restrict__ head_w2, const float* __restrict__ head_b2,
    const float* __restrict__ W_ih0, const float* __restrict__ W_hh0,
    const float* __restrict__ W_ih1, const float* __restrict__ W_hh1,
    float* __restrict__ y)
{
    extern __shared__ __align__(16) uint4 smq[];
    const int tid   = threadIdx.x;
    const int lane  = tid & 31;
    const int w     = tid >> 5;
    const int gw    = w >> 3;            // 0 = layer-0 group, 1 = layer-1 group
    const int wl    = w & 7;
    const int mt    = wl >> 2;
    const int q     = wl & 3;
    const int gid   = lane >> 2;
    const int tig   = lane & 3;
    const int crank = blockIdx.x & 3;
    const int b0    = (blockIdx.x >> 2) * RWS_;

    for (int idx = tid; idx < 96 * H_; idx += NTHR) {
        int g = idx >> 7, k = idx & 127;
        int gt = g >> 5, ul = g & 31;
        int qq = ul >> 3, gidn = ul & 7;
        int kt = k >> 4, klo = k & 15;
        int boff = ((klo >> 3) & 1) * 4 + (klo & 1) * 2;
        int slot = ((qq * 8 + kt) * 3 + gt) * 32 + gidn * 4 + ((klo >> 1) & 3);
        size_t grow = (size_t)(gt * H_ + crank * UN_ + ul);
        wsplit(smq + QB_HH0 + slot, boff, W_hh0[grow * H_ + k]);
        wsplit(smq + QB_IH1 + slot, boff, W_ih1[grow * H_ + k]);
        wsplit(smq + QB_HH1 + slot, boff, W_hh1[grow * H_ + k]);
    }
    for (int idx = tid; idx < 96 * 48; idx += NTHR) {
        int g = idx / 48, k = idx % 48;
        int gt = g >> 5, ul = g & 31;
        int qq = ul >> 3, gidn = ul & 7;
        int kt = k >> 4, klo = k & 15;
        int boff = ((klo >> 3) & 1) * 4 + (klo & 1) * 2;
        int slot = ((qq * 3 + kt) * 3 + gt) * 32 + gidn * 4 + ((klo >> 1) & 3);
        size_t grow = (size_t)(gt * H_ + crank * UN_ + ul);
        wsplit(smq + QB_IH0 + slot, boff, W_ih0[grow * 48 + k]);
    }
    for (int i = tid; i < 12288; i += NTHR)
        ((uint32_t*)(smq + QA_H0))[i] = 0;

    if (tid < 256) {   // embed into x-plane kt=2 (constant)
        int r = tid >> 3, kp = 16 + (tid & 7);
        int e0 = 2 * kp - 32;
        float f0 = embed[(size_t)ticker[b0 + r] * E_ + e0];
        float f1 = embed[(size_t)ticker[b0 + r] * E_ + e0 + 1];
        int mtt = r >> 4, rl = r & 15;
        int ln = (rl & 7) * 4 + (kp & 3), h2 = (kp >> 2) & 1, kt = kp >> 3;
        uint4* sp = smq + QA_X + ((mtt * 3 + kt) * 2 + h2) * 32 + ln;
        uint32_t hi, lo; split2(f0, f1, hi, lo);
        ((uint32_t*)sp)[rl >> 3] = hi;
        ((uint32_t*)sp)[2 + (rl >> 3)] = lo;
    }
    // x staging geometry (iteration-invariant; one float2 per thread)
    const int xr = tid >> 4, xkp = tid & 15;
    const int xrl = xr & 15;
    uint32_t* xdst;
    {
        int mtt = xr >> 4;
        int ln = (xrl & 7) * 4 + (xkp & 3), h2 = (xkp >> 2) & 1, kt = xkp >> 3;
        xdst = (uint32_t*)(smq + QA_X + ((mtt * 3 + kt) * 2 + h2) * 32 + ln);
    }
    const int xo_hi = xrl >> 3, xo_lo = 2 + (xrl >> 3);
    const float* xsrc = x + (size_t)(b0 + xr) * T_ * F_ + 2 * xkp;
    {   // x(t=0)
        float2 v = *(const float2*)xsrc;
        uint32_t hi, lo; split2(v.x, v.y, hi, lo);
        xdst[xo_hi] = hi; xdst[xo_lo] = lo;
    }
    xsrc += F_;   // now points at x(1)

    const int ug0 = crank * 32 + q * 8 + 2 * tig;
    float brb[2], bzb[2], bxnb[2], bhnb[2];
#pragma unroll
    for (int e = 0; e < 2; ++e) {
        int j = ug0 + e;
        if (gw == 0) {
            brb[e]  = b_ih0[j] + b_hh0[j];
            bzb[e]  = b_ih0[H_ + j] + b_hh0[H_ + j];
            bxnb[e] = b_ih0[2 * H_ + j];
            bhnb[e] = b_hh0[2 * H_ + j];
        } else {
            brb[e]  = b_ih1[j] + b_hh1[j];
            bzb[e]  = b_ih1[H_ + j] + b_hh1[H_ + j];
            bxnb[e] = b_ih1[2 * H_ + j];
            bhnb[e] = b_hh1[2 * H_ + j];
        }
    }
    float hown[4] = {0.f, 0.f, 0.f, 0.f};

    const int pkt = crank * 2 + (q >> 1);
    const int ph2 = q & 1;
    const uint32_t poff = (uint32_t)(((mt * 8 + pkt) * 2 + ph2) * 32 + lane) * 16u;

    __syncthreads();
    CARRIVE(); CWAIT();        // all init visible cluster-wide
    CARRIVE();                 // prime S2: first in-loop W(S2) pairs with this

#pragma unroll 1
    for (int i = 0; i <= T_; ++i) {
        const uint4* H0cur = smq + QA_H0 + (i & 1) * 1024 + mt * 512;
        uint4* H0nxt_pl    = smq + QA_H0 + ((i + 1) & 1) * 1024;
        float hv[4];
        const bool active = (gw == 0) ? (i < T_) : (i >= 1);
        const bool dox = (i + 1 < T_);

        // prefetch x(i+1) into registers (latency hidden under M1/M2)
        float2 xv;
        if (dox) xv = *(const float2*)xsrc;

        float Dr0[4] = {0,0,0,0}, Dz0[4] = {0,0,0,0}, Dnx[4] = {0,0,0,0};
        float Dr1[4] = {0,0,0,0}, Dz1[4] = {0,0,0,0}, Dnh[4] = {0,0,0,0};

        // ---- M1: h0-dependent matrix (certified by W(S1) of prev iter) ----
        if (active) {
            if (gw == 0)
                mma_mat<8>(smq + QB_HH0 + q * 768, H0cur, lane, Dr1, Dz1, Dnh);
            else
                mma_mat<8>(smq + QB_IH1 + q * 768, H0cur, lane, Dr0, Dz0, Dnx);
        }
        CWAIT();   // W(S2)(i-1): x(i) [gw0] and h1(i-2) [gw1] certified

        // ---- M2 ----
        if (active) {
            if (gw == 0)
                mma_mat<3>(smq + QB_IH0 + q * 288, smq + QA_X + mt * 192, lane,
                           Dr0, Dz0, Dnx);
            else
                mma_mat<8>(smq + QB_HH1 + q * 768, smq + QA_H1 + mt * 512, lane,
                           Dr1, Dz1, Dnh);
#pragma unroll
            for (int e = 0; e < 4; ++e) {
                float R = sigmoidf_(Dr0[e] + Dr1[e] + brb[e & 1]);
                float Z = sigmoidf_(Dz0[e] + Dz1[e] + bzb[e & 1]);
                float N = tanhf_(Dnx[e] + bxnb[e & 1] + R * (Dnh[e] + bhnb[e & 1]));
                hv[e] = N + Z * (hown[e] - N);
                hown[e] = hv[e];
            }
            if (gw == 0) {   // publish h0(i) into the free buffer
                uint32_t a0h, a0l, a1h, a1l;
                split2(hv[0], hv[1], a0h, a0l);
                split2(hv[2], hv[3], a1h, a1l);
                uint32_t la = smem_u32(H0nxt_pl) + poff;
#pragma unroll
                for (int rk = 0; rk < CL_; ++rk)
                    stc_v4(la, rk, a0h, a1h, a0l, a1l);
            }
        }
        CARRIVE();          // A(S1)
        __syncthreads();    // all CTA warps past x(i) reads
        if (dox) {          // stage x(i+1) inside the S1 window
            uint32_t hi, lo; split2(xv.x, xv.y, hi, lo);
            xdst[xo_hi] = hi; xdst[xo_lo] = lo;
            xsrc += F_;
        }
        CWAIT();            // W(S1): h0(i) visible everywhere

        if (gw == 1 && i >= 1) {   // publish h1(i-1); WAR safe past S1
            uint32_t a0h, a0l, a1h, a1l;
            split2(hv[0], hv[1], a0h, a0l);
            split2(hv[2], hv[3], a1h, a1l);
            uint32_t la = smem_u32(smq + QA_H1) + poff;
#pragma unroll
            for (int rk = 0; rk < CL_; ++rk)
                stc_v4(la, rk, a0h, a1h, a0l, a1l);
            if (i == T_) {   // final h1 -> fp32 scratch for head
                float* scr = (float*)(smq + QSCR);
#pragma unroll
                for (int e = 0; e < 4; ++e) {
                    int row = mt * 16 + gid + (e >> 1) * 8;
                    int ug  = ug0 + (e & 1);
                    uint32_t la2 = smem_u32(scr + (row & 7) * H_ + ug);
                    stc_f32(la2, row >> 3, hv[e]);
                }
            }
        }
        CARRIVE();          // A(S2): h1(i-1)/x(i+1) publish issued
    }
    CWAIT();                // final W(S2): scratch + h1 visible

    // ---- head ----
    const float* scr = (const float*)(smq + QSCR);
    float* hid = (float*)(smq + QA_X);
    if (tid < H_) {
        const float w2  = head_w2[tid];
        const float b1v = head_b1[tid];
        float acc[8];
#pragma unroll
        for (int r = 0; r < 8; ++r) acc[r] = b1v;
        for (int k4 = 0; k4 < 32; ++k4) {
            float4 wv = *(const float4*)(head_w1 + (size_t)tid * H_ + k4 * 4);
#pragma unroll
            for (int r = 0; r < 8; ++r) {
                float4 v = *(const float4*)(scr + r * H_ + k4 * 4);
                acc[r] += wv.x * v.x + wv.y * v.y + wv.z * v.z + wv.w * v.w;
            }
        }
#pragma unroll
        for (int r = 0; r < 8; ++r)
            hid[r * H_ + tid] = fmaxf(acc[r], 0.f) * w2;
    }
    __syncthreads();
    if (tid < 8) {
        float acc = head_b2[0];
        for (int k = 0; k < H_; ++k) acc += hid[tid * H_ + k];
        y[b0 + crank * 8 + tid] = acc;
    }
}

extern "C" void kernel_launch(void* const* d_in, const int* in_sizes, int n_in,
                              void* d_out, int out_size) {
    const float* x       = (const float*)d_in[0];
    const int*   ticker  = (const int*)  d_in[1];
    const float* embed   = (const float*)d_in[2];
    const float* W_ih0   = (const float*)d_in[3];
    const float* W_hh0   = (const float*)d_in[4];
    const float* b_ih0   = (const float*)d_in[5];
    const float* b_hh0   = (const float*)d_in[6];
    const float* W_ih1   = (const float*)d_in[7];
    const float* W_hh1   = (const float*)d_in[8];
    const float* b_ih1   = (const float*)d_in[9];
    const float* b_hh1   = (const float*)d_in[10];
    const float* head_w1 = (const float*)d_in[11];
    const float* head_b1 = (const float*)d_in[12];
    const float* head_w2 = (const float*)d_in[13];
    const float* head_b2 = (const float*)d_in[14];

    cudaFuncSetAttribute(gru_kernel,
                         cudaFuncAttributeMaxDynamicSharedMemorySize, SMEM_BYTES);

    cudaLaunchConfig_t cfg = {};
    cfg.gridDim  = dim3(NCTA, 1, 1);
    cfg.blockDim = dim3(NTHR, 1, 1);
    cfg.dynamicSmemBytes = SMEM_BYTES;
    cfg.stream = 0;
    cudaLaunchAttribute attr[1];
    attr[0].id = cudaLaunchAttributeClusterDimension;
    attr[0].val.clusterDim.x = CL_;
    attr[0].val.clusterDim.y = 1;
    attr[0].val.clusterDim.z = 1;
    cfg.attrs = attr;
    cfg.numAttrs = 1;

    cudaLaunchKernelEx(&cfg, gru_kernel,
                       x, ticker, embed,
                       b_ih0, b_hh0, b_ih1, b_hh1,
                       head_w1, head_b1, head_w2, head_b2,
                       W_ih0, W_hh0, W_ih1, W_hh1,
                       (float*)d_out);
}